// round 15
// baseline (speedup 1.0000x reference)
#include <cuda_runtime.h>
#include <cuda_fp16.h>
#include <math.h>
#include <stdint.h>

#define DIMC 256
#define NTOK 128
#define BAT  8
#define HID  1024
#define EPSV 1e-5f
#define ASCALE 0.17677669529663687f

#define LDAh 264    // sAh row stride (halfs)
#define LDHh 136    // sHh row stride (halfs)
#define LDBh 72     // B chunk row stride (halfs)
#define KCH  64     // k per chunk (halfs)
#define BUFSZ 18432 // bytes per B buffer

// -------- device scratch --------
__device__ float g_x1 [BAT*NTOK*DIMC];
__device__ float g_q  [BAT*NTOK*DIMC];
__device__ float g_k  [BAT*NTOK*DIMC];
__device__ float g_v  [BAT*NTOK*DIMC];
__device__ float g_agg[BAT*NTOK*DIMC];
__device__ __half g_WeH [DIMC*DIMC];    // edge We   [n=256][k=256]
__device__ __half g_WoeH[DIMC*DIMC];    // edge Woe  [n=256][k=256]
__device__ __half g_W1H [HID*DIMC];     // EDGE mlp2_w1 [n=1024][k=256]
__device__ __half g_W2H [DIMC*HID];     // EDGE mlp2_w2 [n=256][k=1024]
__device__ __half g_N1H [HID*DIMC];     // NODE mlp1_w1 [n=1024][k=256]
__device__ __half g_N2H [DIMC*HID];     // NODE mlp1_w2 [n=256][k=1024]
__device__ __half g_WonH[DIMC*DIMC];    // Won [n=256][k=256]
__device__ __half g_QKVH[3*DIMC*DIMC];  // [n=768][k=256] (q,k,v stacked)

// -------- PTX helpers --------
__device__ __forceinline__ void mma16(float* d, const uint32_t* a, const uint32_t* b){
    asm volatile("mma.sync.aligned.m16n8k16.row.col.f32.f16.f16.f32 "
        "{%0,%1,%2,%3},{%4,%5,%6,%7},{%8,%9},{%0,%1,%2,%3};"
        : "+f"(d[0]),"+f"(d[1]),"+f"(d[2]),"+f"(d[3])
        : "r"(a[0]),"r"(a[1]),"r"(a[2]),"r"(a[3]),"r"(b[0]),"r"(b[1]));
}
__device__ __forceinline__ void ldsm4(uint32_t* r, uint32_t addr){
    asm volatile("ldmatrix.sync.aligned.m8n8.x4.shared.b16 {%0,%1,%2,%3}, [%4];"
        : "=r"(r[0]),"=r"(r[1]),"=r"(r[2]),"=r"(r[3]) : "r"(addr));
}
__device__ __forceinline__ void cpa16(uint32_t dst, const void* src){
    asm volatile("cp.async.cg.shared.global [%0], [%1], 16;" :: "r"(dst), "l"(src));
}
#define CP_COMMIT() asm volatile("cp.async.commit_group;" ::: "memory")
#define CP_WAIT(n)  asm volatile("cp.async.wait_group %0;" :: "n"(n) : "memory")

#define ZEROC(c, MF, NF) { _Pragma("unroll") for (int _m=0;_m<MF;_m++) _Pragma("unroll") for (int _n=0;_n<NF;_n++) _Pragma("unroll") for (int _u=0;_u<4;_u++) (c)[_m][_n][_u]=0.f; }

// k-chunked GEMM, 512 threads, fp16 operands, fp32 accum; 2-deep cp.async ring.
__device__ __forceinline__ void gemm_h(
    uint32_t aLane, int ldah,
    const __half* __restrict__ gB, int ldgb, int k0, int nkc,
    uint32_t sB_u, uint32_t bLane,
    float c[2][4][4], int tid)
{
    const __half* src0 = gB + k0;
    #define STAGE(kc, s) { \
        const __half* _s = src0 + (kc)*KCH; \
        uint32_t _d = sB_u + (uint32_t)(s)*BUFSZ; \
        _Pragma("unroll") \
        for (int _j = 0; _j < 2; _j++){ \
            int _ii = tid + _j*512; \
            int _n = _ii >> 3, _q = _ii & 7; \
            cpa16(_d + (uint32_t)(_n*LDBh + _q*8)*2, _s + (size_t)_n*ldgb + _q*8); \
        } \
        CP_COMMIT(); }
    STAGE(0, 0);
    for (int kc = 0; kc < nkc; kc++){
        __syncthreads();
        if (kc + 1 < nkc){ STAGE(kc+1, (kc+1)&1); CP_WAIT(1); }
        else             { CP_WAIT(0); }
        __syncthreads();
        uint32_t bBuf = bLane + (uint32_t)(kc & 1)*BUFSZ;
        #pragma unroll
        for (int ks = 0; ks < KCH/16; ks++){
            uint32_t a[2][4];
            #pragma unroll
            for (int mf = 0; mf < 2; mf++)
                ldsm4(a[mf], aLane + (uint32_t)(mf*16*ldah + kc*KCH + ks*16)*2);
            #pragma unroll
            for (int np = 0; np < 2; np++){
                uint32_t b4[4];
                ldsm4(b4, bBuf + (uint32_t)(np*16*LDBh + ks*16)*2);
                uint32_t bx[2] = { b4[0], b4[2] };
                uint32_t by[2] = { b4[1], b4[3] };
                #pragma unroll
                for (int mf = 0; mf < 2; mf++){
                    mma16(c[mf][2*np+0], a[mf], bx);
                    mma16(c[mf][2*np+1], a[mf], by);
                }
            }
        }
    }
    #undef STAGE
}

// ================= prep: transpose + fp16 weights =================
__global__ __launch_bounds__(256) void prep_kernel(
    const float* __restrict__ We, const float* __restrict__ Woe,
    const float* __restrict__ w1, const float* __restrict__ w2,
    const float* __restrict__ n1, const float* __restrict__ n2,
    const float* __restrict__ Won,
    const float* __restrict__ Wq, const float* __restrict__ Wk,
    const float* __restrict__ Wv)
{
    int idx = blockIdx.x*256 + threadIdx.x;   // 0..262143
    if (idx < DIMC*DIMC){
        int n = idx >> 8, k = idx & 255;
        g_WeH [idx] = __float2half_rn(We [k*DIMC + n]);
        g_WoeH[idx] = __float2half_rn(Woe[k*DIMC + n]);
        g_WonH[idx] = __float2half_rn(Won[k*DIMC + n]);
    }
    {   int n = idx >> 8, k = idx & 255;
        g_W1H[idx] = __float2half_rn(w1[(size_t)k*HID + n]);
        g_N1H[idx] = __float2half_rn(n1[(size_t)k*HID + n]); }
    {   int n = idx >> 10, k = idx & 1023;
        g_W2H[idx] = __float2half_rn(w2[(size_t)k*DIMC + n]);
        g_N2H[idx] = __float2half_rn(n2[(size_t)k*DIMC + n]); }
    if (idx < 3*DIMC*DIMC){
        int n = idx >> 8, k = idx & 255;
        int mat = n >> 8, col = n & 255;
        const float* W = (mat == 0) ? Wq : (mat == 1) ? Wk : Wv;
        g_QKVH[idx] = __float2half_rn(W[k*DIMC + col]);
    }
}

// full-batch B preload macro (flat arrays, constant indices)
#define PRELOAD_B2(bf, NK, base, ldb) \
    _Pragma("unroll") \
    for (int _kk = 0; _kk < NK; _kk++) \
        _Pragma("unroll") \
        for (int _nf = 0; _nf < 2; _nf++){ \
            const __half* _bp = (base) + (size_t)_nf*8*(ldb) + _kk*16; \
            bf[_kk][_nf][0] = *(const uint32_t*)_bp; \
            bf[_kk][_nf][1] = *(const uint32_t*)(_bp + 8); \
        }

// ================= kernel 1: LN1 + q/k/v (fp16 mma, 16 rows/CTA, 64 CTAs) =================
__global__ __launch_bounds__(512) void node_pre_kernel(
    const float* __restrict__ x,
    const float* __restrict__ bq, const float* __restrict__ bk,
    const float* __restrict__ bv,
    const float* __restrict__ ln1s, const float* __restrict__ ln1b)
{
    __shared__ __align__(16) __half sA[16*LDAh];
    int tid = threadIdx.x, lane = tid & 31, w = tid >> 5;   // 16 warps
    int r0 = blockIdx.x * 16;
    int sub = lane >> 3, rin = lane & 7;

    // LN1: warp w -> row r0+w (all 16 rows real)
    {
        const float* xr = x + (size_t)(r0 + w) * DIMC;
        float vals[8], s = 0.f, sq = 0.f;
        #pragma unroll
        for (int u = 0; u < 8; u++){ vals[u] = xr[lane + u*32]; s += vals[u]; sq += vals[u]*vals[u]; }
        #pragma unroll
        for (int o = 16; o > 0; o >>= 1){ s += __shfl_xor_sync(~0u,s,o); sq += __shfl_xor_sync(~0u,sq,o); }
        float mean = s * (1.f/DIMC);
        float rstd = rsqrtf(sq*(1.f/DIMC) - mean*mean + EPSV);
        #pragma unroll
        for (int u = 0; u < 8; u++){
            int c = lane + u*32;
            float v = (vals[u]-mean)*rstd*ln1s[c] + ln1b[c];
            g_x1[(r0+w)*DIMC + c] = v;
            sA[w*LDAh + c] = __float2half_rn(v);
        }
    }
    __syncthreads();

    uint32_t aLane = (uint32_t)__cvta_generic_to_shared(sA)
                   + (uint32_t)((((sub&1)*8 + rin)*LDAh + (sub>>1)*8)*2);
    int g = lane >> 2, t2 = (lane & 3)*2;

    // warp w covers 16 n-cols (2 frags); all 16 m-rows real
    #pragma unroll
    for (int pass = 0; pass < 3; pass++){
        float c[2][4];
        #pragma unroll
        for (int nf = 0; nf < 2; nf++)
            #pragma unroll
            for (int u = 0; u < 4; u++) c[nf][u] = 0.f;
        const __half* base = g_QKVH + (size_t)(pass*256 + w*16 + (lane>>2))*DIMC + (lane&3)*2;
        #pragma unroll
        for (int kk = 0; kk < 16; kk++){
            uint32_t a[4];
            ldsm4(a, aLane + (uint32_t)(kk*16*2));
            #pragma unroll
            for (int nf = 0; nf < 2; nf++){
                const __half* bp = base + (size_t)nf*8*DIMC + kk*16;
                uint32_t b[2] = { *(const uint32_t*)bp, *(const uint32_t*)(bp + 8) };
                mma16(c[nf], a, b);
            }
        }
        const float* bias = (pass == 0) ? bq : (pass == 1) ? bk : bv;
        float* dst = (pass == 0) ? g_q : (pass == 1) ? g_k : g_v;
        #pragma unroll
        for (int nf = 0; nf < 2; nf++){
            int col = w*16 + nf*8 + t2;
            *(float2*)(dst + (size_t)(r0+g)*DIMC + col) =
                make_float2(c[nf][0] + bias[col], c[nf][1] + bias[col+1]);
            *(float2*)(dst + (size_t)(r0+g+8)*DIMC + col) =
                make_float2(c[nf][2] + bias[col], c[nf][3] + bias[col+1]);
        }
    }
}

// ================= kernel 2: edge mega-kernel (fp16 mma, fp32 residuals) =================
__global__ __launch_bounds__(512, 1) void edge_kernel(
    const float* __restrict__ y,
    const float* __restrict__ be,  const float* __restrict__ boe,
    const float* __restrict__ b1,  const float* __restrict__ b2,
    const float* __restrict__ ln4s, const float* __restrict__ ln4b,
    const float* __restrict__ ln6s, const float* __restrict__ ln6b,
    float* __restrict__ yout)
{
    extern __shared__ char smem[];
    __half* sAh = (__half*)smem;                    // 67584
    __half* sRh = (__half*)(smem + 67584);          // 67584
    __half* sHh = (__half*)(smem + 135168);         // 34816
    char*   sBc = smem + 169984;                    // 36864
    float*  sS  = (float*)(smem + 206848);          // 512 f
    float*  sAg = (float*)(smem + 208896);          // 512 f
    float*  sQ  = (float*)(smem + 210944);          // 256 f

    uint32_t sA_u = (uint32_t)__cvta_generic_to_shared(sAh);
    uint32_t sH_u = (uint32_t)__cvta_generic_to_shared(sHh);
    uint32_t sB_u = (uint32_t)__cvta_generic_to_shared(sBc);

    int tid = threadIdx.x, lane = tid & 31, w = tid >> 5;
    int wm = (w >> 2) * 32, wn = w & 3;
    int g = lane >> 2, t = lane & 3;
    int sub = lane >> 3, rin = lane & 7;
    int bi = blockIdx.x, b = bi >> 7;
    const float* yblk = y + (size_t)bi * NTOK * DIMC;

    uint32_t aLaneA = sA_u + (uint32_t)(((wm + (sub&1)*8 + rin)*LDAh + (sub>>1)*8)*2);
    uint32_t aLaneH = sH_u + (uint32_t)(((wm + (sub&1)*8 + rin)*LDHh + (sub>>1)*8)*2);
    uint32_t bLane  = sB_u + (uint32_t)(((wn*32 + (sub&1)*8 + rin)*LDBh + (sub>>1)*8)*2);

    if (tid < 256) sQ[tid] = g_q[bi*DIMC + tid] * ASCALE;
    {
        const float4* y4 = (const float4*)yblk;
        for (int i = tid; i < 8192; i += 512){
            int r = i >> 6, kq = (i & 63) << 2;
            float4 v = y4[i];
            __half2* d = (__half2*)(sAh + r*LDAh + kq);
            d[0] = __floats2half2_rn(v.x, v.y);
            d[1] = __floats2half2_rn(v.z, v.w);
        }
    }

    float cE0[2][4][4], cE1[2][4][4];

    // ---- GEMM1: e = y @ We ----
    ZEROC(cE0, 2, 4); ZEROC(cE1, 2, 4);
    gemm_h(aLaneA, LDAh, g_WeH,            DIMC, 0, 4, sB_u, bLane, cE0, tid);
    gemm_h(aLaneA, LDAh, g_WeH + 128*DIMC, DIMC, 0, 4, sB_u, bLane, cE1, tid);
    __syncthreads();
    #pragma unroll
    for (int nc = 0; nc < 2; nc++)
    #pragma unroll
    for (int mf = 0; mf < 2; mf++)
    #pragma unroll
    for (int nf = 0; nf < 4; nf++)
    #pragma unroll
    for (int hh = 0; hh < 2; hh++){
        float* cc = nc ? cE1[mf][nf] : cE0[mf][nf];
        int r = wm + mf*16 + g + hh*8;
        int col = nc*128 + wn*32 + nf*8 + 2*t;
        float e0 = cc[2*hh+0] + be[col];
        float e1 = cc[2*hh+1] + be[col+1];
        float2 kv = *(const float2*)(g_k + (size_t)(b*NTOK + r)*DIMC + col);
        float v0 = sQ[col]  *kv.x*(e0 + 1.f)*e0;
        float v1 = sQ[col+1]*kv.y*(e1 + 1.f)*e1;
        *(__half2*)(sAh + r*LDAh + col) = __floats2half2_rn(v0, v1);
    }
    __syncthreads();

    // ---- softmax over j + agg ----
    {
        int half_ = tid >> 8, c = tid & 255;
        int j0 = half_*64;
        float mx = -1e30f;
        for (int j = j0; j < j0+64; j++) mx = fmaxf(mx, __half2float(sAh[j*LDAh + c]));
        sS[tid] = mx;
        __syncthreads();
        float M = fmaxf(sS[c], sS[256 + c]);
        float s = 0.f, agv = 0.f;
        for (int j = j0; j < j0+64; j++){
            float p = __expf(__half2float(sAh[j*LDAh + c]) - M);
            s += p;
            agv += p * g_v[(size_t)(b*NTOK + j)*DIMC + c];
        }
        __syncthreads();
        sS[tid] = s; sAg[tid] = agv;
        __syncthreads();
        if (tid < 256)
            g_agg[bi*DIMC + tid] = (sAg[tid] + sAg[256+tid]) / (sS[tid] + sS[256+tid]);
        __syncthreads();
    }

    // ---- GEMM2: edge_out = attn @ Woe ----
    ZEROC(cE0, 2, 4); ZEROC(cE1, 2, 4);
    gemm_h(aLaneA, LDAh, g_WoeH,            DIMC, 0, 4, sB_u, bLane, cE0, tid);
    gemm_h(aLaneA, LDAh, g_WoeH + 128*DIMC, DIMC, 0, 4, sB_u, bLane, cE1, tid);

    // ---- epilogue2 + LN4 in fp32 registers ----
    {
        float ps[2][2] = {}, pq[2][2] = {};
        #pragma unroll
        for (int nc = 0; nc < 2; nc++)
        #pragma unroll
        for (int mf = 0; mf < 2; mf++)
        #pragma unroll
        for (int nf = 0; nf < 4; nf++)
        #pragma unroll
        for (int hh = 0; hh < 2; hh++){
            float* cc = nc ? cE1[mf][nf] : cE0[mf][nf];
            int r = wm + mf*16 + g + hh*8;
            int col = nc*128 + wn*32 + nf*8 + 2*t;
            float2 yv = *(const float2*)(yblk + (size_t)r*DIMC + col);
            float v0 = cc[2*hh+0] + boe[col]   + yv.x;
            float v1 = cc[2*hh+1] + boe[col+1] + yv.y;
            cc[2*hh+0] = v0; cc[2*hh+1] = v1;
            ps[mf][hh] += v0 + v1; pq[mf][hh] += v0*v0 + v1*v1;
        }
        #pragma unroll
        for (int mf = 0; mf < 2; mf++)
        #pragma unroll
        for (int hh = 0; hh < 2; hh++){
            ps[mf][hh] += __shfl_xor_sync(~0u, ps[mf][hh], 1);
            ps[mf][hh] += __shfl_xor_sync(~0u, ps[mf][hh], 2);
            pq[mf][hh] += __shfl_xor_sync(~0u, pq[mf][hh], 1);
            pq[mf][hh] += __shfl_xor_sync(~0u, pq[mf][hh], 2);
        }
        if (t == 0){
            #pragma unroll
            for (int mf = 0; mf < 2; mf++)
            #pragma unroll
            for (int hh = 0; hh < 2; hh++){
                int r = wm + mf*16 + g + hh*8;
                sS [wn*128 + r] = ps[mf][hh];
                sAg[wn*128 + r] = pq[mf][hh];
            }
        }
        __syncthreads();
        #pragma unroll
        for (int mf = 0; mf < 2; mf++)
        #pragma unroll
        for (int hh = 0; hh < 2; hh++){
            int r = wm + mf*16 + g + hh*8;
            float S = sS[r] + sS[128+r] + sS[256+r] + sS[384+r];
            float Q = sAg[r] + sAg[128+r] + sAg[256+r] + sAg[384+r];
            float mean = S * (1.f/256.f);
            float rstd = rsqrtf(Q*(1.f/256.f) - mean*mean + EPSV);
            #pragma unroll
            for (int nc = 0; nc < 2; nc++)
            #pragma unroll
            for (int nf = 0; nf < 4; nf++){
                float* cc = nc ? cE1[mf][nf] : cE0[mf][nf];
                int col = nc*128 + wn*32 + nf*8 + 2*t;
                float v0 = (cc[2*hh+0] - mean)*rstd*ln4s[col]   + ln4b[col];
                float v1 = (cc[2*hh+1] - mean)*rstd*ln4s[col+1] + ln4b[col+1];
                __half h0 = __float2half_rn(v0), h1 = __float2half_rn(v1);
                *(__half2*)(sAh + r*LDAh + col) = __halves2half2(h0, h1);
                *(__half2*)(sRh + r*LDAh + col) =
                    __floats2half2_rn(v0 - __half2float(h0), v1 - __half2float(h1));
            }
        }
    }

    // ---- MLP ----
    float cM0[2][4][4], cM1[2][4][4];
    ZEROC(cM0, 2, 4); ZEROC(cM1, 2, 4);
    for (int ht = 0; ht < 8; ht++){
        float cH[2][4][4];
        ZEROC(cH, 2, 4);
        gemm_h(aLaneA, LDAh, g_W1H + (size_t)ht*128*DIMC, DIMC, 0, 4, sB_u, bLane, cH, tid);
        #pragma unroll
        for (int mf = 0; mf < 2; mf++)
        #pragma unroll
        for (int nf = 0; nf < 4; nf++)
        #pragma unroll
        for (int hh = 0; hh < 2; hh++){
            int r = wm + mf*16 + g + hh*8;
            int col = wn*32 + nf*8 + 2*t;
            float h0 = fmaxf(cH[mf][nf][2*hh+0] + b1[ht*128 + col],     0.f);
            float h1 = fmaxf(cH[mf][nf][2*hh+1] + b1[ht*128 + col + 1], 0.f);
            *(__half2*)(sHh + r*LDHh + col) = __floats2half2_rn(h0, h1);
        }
        gemm_h(aLaneH, LDHh, g_W2H,                   HID, ht*128, 2, sB_u, bLane, cM0, tid);
        gemm_h(aLaneH, LDHh, g_W2H + (size_t)128*HID, HID, ht*128, 2, sB_u, bLane, cM1, tid);
    }

    // ---- LN6 -> yout ----
    {
        float ps[2][2] = {}, pq[2][2] = {};
        #pragma unroll
        for (int nc = 0; nc < 2; nc++)
        #pragma unroll
        for (int mf = 0; mf < 2; mf++)
        #pragma unroll
        for (int nf = 0; nf < 4; nf++)
        #pragma unroll
        for (int hh = 0; hh < 2; hh++){
            float* cc = nc ? cM1[mf][nf] : cM0[mf][nf];
            int r = wm + mf*16 + g + hh*8;
            int col = nc*128 + wn*32 + nf*8 + 2*t;
            float2 hi = __half22float2(*(__half2*)(sAh + r*LDAh + col));
            float2 lo = __half22float2(*(__half2*)(sRh + r*LDAh + col));
            float v0 = cc[2*hh+0] + b2[col]   + hi.x + lo.x;
            float v1 = cc[2*hh+1] + b2[col+1] + hi.y + lo.y;
            cc[2*hh+0] = v0; cc[2*hh+1] = v1;
            ps[mf][hh] += v0 + v1; pq[mf][hh] += v0*v0 + v1*v1;
        }
        #pragma unroll
        for (int mf = 0; mf < 2; mf++)
        #pragma unroll
        for (int hh = 0; hh < 2; hh++){
            ps[mf][hh] += __shfl_xor_sync(~0u, ps[mf][hh], 1);
            ps[mf][hh] += __shfl_xor_sync(~0u, ps[mf][hh], 2);
            pq[mf][hh] += __shfl_xor_sync(~0u, pq[mf][hh], 1);
            pq[mf][hh] += __shfl_xor_sync(~0u, pq[mf][hh], 2);
        }
        __syncthreads();
        if (t == 0){
            #pragma unroll
            for (int mf = 0; mf < 2; mf++)
            #pragma unroll
            for (int hh = 0; hh < 2; hh++){
                int r = wm + mf*16 + g + hh*8;
                sS [wn*128 + r] = ps[mf][hh];
                sAg[wn*128 + r] = pq[mf][hh];
            }
        }
        __syncthreads();
        float* youtb = yout + (size_t)bi*NTOK*DIMC;
        #pragma unroll
        for (int mf = 0; mf < 2; mf++)
        #pragma unroll
        for (int hh = 0; hh < 2; hh++){
            int r = wm + mf*16 + g + hh*8;
            float S = sS[r] + sS[128+r] + sS[256+r] + sS[384+r];
            float Q = sAg[r] + sAg[128+r] + sAg[256+r] + sAg[384+r];
            float mean = S * (1.f/256.f);
            float rstd = rsqrtf(Q*(1.f/256.f) - mean*mean + EPSV);
            #pragma unroll
            for (int nc = 0; nc < 2; nc++)
            #pragma unroll
            for (int nf = 0; nf < 4; nf++){
                float* cc = nc ? cM1[mf][nf] : cM0[mf][nf];
                int col = nc*128 + wn*32 + nf*8 + 2*t;
                float v0 = (cc[2*hh+0] - mean)*rstd*ln6s[col]   + ln6b[col];
                float v1 = (cc[2*hh+1] - mean)*rstd*ln6s[col+1] + ln6b[col+1];
                *(float2*)(youtb + (size_t)r*DIMC + col) = make_float2(v0, v1);
            }
        }
    }
}

// ================= kernel 3: node post (fp16 mma, 16 rows/CTA, 64 CTAs) =================
__global__ __launch_bounds__(512, 1) void node_post_kernel(
    const float* __restrict__ bon,
    const float* __restrict__ b1, const float* __restrict__ b2,
    const float* __restrict__ ln3s, const float* __restrict__ ln3b,
    const float* __restrict__ ln5s, const float* __restrict__ ln5b,
    float* __restrict__ xout)
{
    __shared__ __align__(16) __half sA[16*LDAh];
    __shared__ __align__(16) __half sH[16*LDHh];
    __shared__ float  sX[16*260];
    __shared__ float  sRed[2][256];

    int tid = threadIdx.x, lane = tid & 31, w = tid >> 5;   // 16 warps
    int r0 = blockIdx.x * 16;
    int sub = lane >> 3, rin = lane & 7;
    int g = lane >> 2, t2 = (lane & 3)*2;

    // load agg rows 0..15 (fp16) -- all 16 rows real, no padding
    for (int i = tid; i < 16*256; i += 512){
        int r = i >> 8, c = i & 255;
        sA[r*LDAh + c] = __float2half_rn(g_agg[(size_t)(r0+r)*DIMC + c]);
    }
    __syncthreads();

    uint32_t aLane = (uint32_t)__cvta_generic_to_shared(sA)
                   + (uint32_t)((((sub&1)*8 + rin)*LDAh + (sub>>1)*8)*2);
    uint32_t hLane = (uint32_t)__cvta_generic_to_shared(sH)
                   + (uint32_t)((((sub&1)*8 + rin)*LDHh + (sub>>1)*8)*2);

    // GEMM: x2pre = agg @ Won -- warp covers 16 n-cols; FULL B preload
    float c1[2][4];
    #pragma unroll
    for (int nf = 0; nf < 2; nf++)
        #pragma unroll
        for (int u = 0; u < 4; u++) c1[nf][u] = 0.f;
    {
        const __half* base = g_WonH + (size_t)(w*16 + (lane>>2))*DIMC + (lane&3)*2;
        uint32_t bf[16][2][2];
        PRELOAD_B2(bf, 16, base, DIMC);
        #pragma unroll
        for (int kk = 0; kk < 16; kk++){
            uint32_t a[4];
            ldsm4(a, aLane + (uint32_t)(kk*16*2));
            #pragma unroll
            for (int nf = 0; nf < 2; nf++)
                mma16(c1[nf], a, bf[kk][nf]);
        }
    }
    // epilogue + LN3 (two row groups: g and g+8)
    {
        float v[2][4], ps[2] = {}, pq[2] = {};
        #pragma unroll
        for (int nf = 0; nf < 2; nf++){
            int col = w*16 + nf*8 + t2;
            float2 xA = *(const float2*)(g_x1 + (size_t)(r0+g)*DIMC + col);
            float2 xB = *(const float2*)(g_x1 + (size_t)(r0+g+8)*DIMC + col);
            v[nf][0] = c1[nf][0] + bon[col]   + xA.x;
            v[nf][1] = c1[nf][1] + bon[col+1] + xA.y;
            v[nf][2] = c1[nf][2] + bon[col]   + xB.x;
            v[nf][3] = c1[nf][3] + bon[col+1] + xB.y;
            ps[0] += v[nf][0] + v[nf][1]; pq[0] += v[nf][0]*v[nf][0] + v[nf][1]*v[nf][1];
            ps[1] += v[nf][2] + v[nf][3]; pq[1] += v[nf][2]*v[nf][2] + v[nf][3]*v[nf][3];
        }
        #pragma unroll
        for (int rg = 0; rg < 2; rg++){
            ps[rg] += __shfl_xor_sync(~0u, ps[rg], 1); pq[rg] += __shfl_xor_sync(~0u, pq[rg], 1);
            ps[rg] += __shfl_xor_sync(~0u, ps[rg], 2); pq[rg] += __shfl_xor_sync(~0u, pq[rg], 2);
        }
        if ((lane & 3) == 0){
            sRed[0][w*16 + g]     = ps[0]; sRed[1][w*16 + g]     = pq[0];
            sRed[0][w*16 + g + 8] = ps[1]; sRed[1][w*16 + g + 8] = pq[1];
        }
        __syncthreads();
        #pragma unroll
        for (int rg = 0; rg < 2; rg++){
            int rr = g + rg*8;
            float S = 0.f, Q = 0.f;
            #pragma unroll
            for (int ww = 0; ww < 16; ww++){ S += sRed[0][ww*16 + rr]; Q += sRed[1][ww*16 + rr]; }
            float mean = S * (1.f/256.f);
            float rstd = rsqrtf(Q*(1.f/256.f) - mean*mean + EPSV);
            #pragma unroll
            for (int nf = 0; nf < 2; nf++){
                int col = w*16 + nf*8 + t2;
                float x0 = (v[nf][2*rg+0] - mean)*rstd*ln3s[col]   + ln3b[col];
                float x1 = (v[nf][2*rg+1] - mean)*rstd*ln3s[col+1] + ln3b[col+1];
                sX[rr*260 + col] = x0; sX[rr*260 + col + 1] = x1;
                *(__half2*)(sA + rr*LDAh + col) = __floats2half2_rn(x0, x1);
            }
        }
        __syncthreads();
    }

    // MLP: ht-interleaved (NODE weights), full B preload per phase, 16 real rows
    float cM[2][4];
    #pragma unroll
    for (int nf = 0; nf < 2; nf++)
        #pragma unroll
        for (int u = 0; u < 4; u++) cM[nf][u] = 0.f;
    for (int ht = 0; ht < 8; ht++){
        // MLP1: 16 warps x 8 cols (1 frag)
        float cH[4];
        #pragma unroll
        for (int u = 0; u < 4; u++) cH[u] = 0.f;
        {
            const __half* base = g_N1H + (size_t)(ht*128 + w*8 + (lane>>2))*DIMC + (lane&3)*2;
            uint32_t bf1[16][2];
            #pragma unroll
            for (int kk = 0; kk < 16; kk++){
                const __half* bp = base + kk*16;
                bf1[kk][0] = *(const uint32_t*)bp;
                bf1[kk][1] = *(const uint32_t*)(bp + 8);
            }
            #pragma unroll
            for (int kk = 0; kk < 16; kk++){
                uint32_t a[4];
                ldsm4(a, aLane + (uint32_t)(kk*16*2));
                mma16(cH, a, bf1[kk]);
            }
        }
        __syncthreads();   // prev MLP2 reads of sH done
        {
            int col = w*8 + t2;
            *(__half2*)(sH + g*LDHh + col) = __floats2half2_rn(
                fmaxf(cH[0] + b1[ht*128 + col],     0.f),
                fmaxf(cH[1] + b1[ht*128 + col + 1], 0.f));
            *(__half2*)(sH + (g+8)*LDHh + col) = __floats2half2_rn(
                fmaxf(cH[2] + b1[ht*128 + col],     0.f),
                fmaxf(cH[3] + b1[ht*128 + col + 1], 0.f));
        }
        __syncthreads();
        // MLP2: 16 warps x 16 cols (2 frags), 8 k-steps
        {
            const __half* base = g_N2H + (size_t)(w*16 + (lane>>2))*HID + ht*128 + (lane&3)*2;
            uint32_t bf2[8][2][2];
            PRELOAD_B2(bf2, 8, base, HID);
            #pragma unroll
            for (int kk = 0; kk < 8; kk++){
                uint32_t a[4];
                ldsm4(a, hLane + (uint32_t)(kk*16*2));
                #pragma unroll
                for (int nf = 0; nf < 2; nf++)
                    mma16(cM[nf], a, bf2[kk][nf]);
            }
        }
    }

    // final: out = cM + b2 + x2 ; LN5 -> xout (two row groups)
    {
        float v[2][4], ps[2] = {}, pq[2] = {};
        #pragma unroll
        for (int nf = 0; nf < 2; nf++){
            int col = w*16 + nf*8 + t2;
            v[nf][0] = cM[nf][0] + b2[col]   + sX[g*260 + col];
            v[nf][1] = cM[nf][1] + b2[col+1] + sX[g*260 + col + 1];
            v[nf][2] = cM[nf][2] + b2[col]   + sX[(g+8)*260 + col];
            v[nf][3] = cM[nf][3] + b2[col+1] + sX[(g+8)*260 + col + 1];
            ps[0] += v[nf][0] + v[nf][1]; pq[0] += v[nf][0]*v[nf][0] + v[nf][1]*v[nf][1];
            ps[1] += v[nf][2] + v[nf][3]; pq[1] += v[nf][2]*v[nf][2] + v[nf][3]*v[nf][3];
        }
        #pragma unroll
        for (int rg = 0; rg < 2; rg++){
            ps[rg] += __shfl_xor_sync(~0u, ps[rg], 1); pq[rg] += __shfl_xor_sync(~0u, pq[rg], 1);
            ps[rg] += __shfl_xor_sync(~0u, ps[rg], 2); pq[rg] += __shfl_xor_sync(~0u, pq[rg], 2);
        }
        __syncthreads();
        if ((lane & 3) == 0){
            sRed[0][w*16 + g]     = ps[0]; sRed[1][w*16 + g]     = pq[0];
            sRed[0][w*16 + g + 8] = ps[1]; sRed[1][w*16 + g + 8] = pq[1];
        }
        __syncthreads();
        #pragma unroll
        for (int rg = 0; rg < 2; rg++){
            int rr = g + rg*8;
            float S = 0.f, Q = 0.f;
            #pragma unroll
            for (int ww = 0; ww < 16; ww++){ S += sRed[0][ww*16 + rr]; Q += sRed[1][ww*16 + rr]; }
            float mean = S * (1.f/256.f);
            float rstd = rsqrtf(Q*(1.f/256.f) - mean*mean + EPSV);
            #pragma unroll
            for (int nf = 0; nf < 2; nf++){
                int col = w*16 + nf*8 + t2;
                float o0 = (v[nf][2*rg+0] - mean)*rstd*ln5s[col]   + ln5b[col];
                float o1 = (v[nf][2*rg+1] - mean)*rstd*ln5s[col+1] + ln5b[col+1];
                *(float2*)(xout + (size_t)(r0+rr)*DIMC + col) = make_float2(o0, o1);
            }
        }
    }
}

// ================= launch =================
extern "C" void kernel_launch(void* const* d_in, const int* in_sizes, int n_in,
                              void* d_out, int out_size)
{
    const float* x    = (const float*)d_in[0];
    const float* y    = (const float*)d_in[1];
    const float* Wq   = (const float*)d_in[2];  const float* bq  = (const float*)d_in[3];
    const float* Wk   = (const float*)d_in[4];  const float* bk  = (const float*)d_in[5];
    const float* Wv   = (const float*)d_in[6];  const float* bv  = (const float*)d_in[7];
    const float* We   = (const float*)d_in[8];  const float* be  = (const float*)d_in[9];
    const float* Woe  = (const float*)d_in[10]; const float* boe = (const float*)d_in[11];
    const float* Won  = (const float*)d_in[12]; const float* bon = (const float*)d_in[13];
    const float* m1w1 = (const float*)d_in[14]; const float* m1b1= (const float*)d_in[15];
    const float* m1w2 = (const float*)d_in[16]; const float* m1b2= (const float*)d_in[17];
    const float* m2w1 = (const float*)d_in[18]; const float* m2b1= (const float*)d_in[19];
    const float* m2w2 = (const float*)d_in[20]; const float* m2b2= (const float*)d_in[21];
    const float* ln1s = (const float*)d_in[22]; const float* ln1b= (const float*)d_in[23];
    const float* ln3s = (const float*)d_in[24]; const float* ln3b= (const float*)d_in[25];
    const float* ln4s = (const float*)d_in[26]; const float* ln4b= (const float*)d_in[27];
    const float* ln5s = (const float*)d_in[28]; const float* ln5b= (const float*)d_in[29];
    const float* ln6s = (const float*)d_in[30]; const float* ln6b= (const float*)d_in[31];

    float* out  = (float*)d_out;
    float* xout = out;                               // (8,128,256)
    float* yout = out + BAT*NTOK*DIMC;               // (8,128,128,256)

    int smem = 211968;
    cudaFuncSetAttribute(edge_kernel, cudaFuncAttributeMaxDynamicSharedMemorySize, smem);

    prep_kernel<<<1024, 256>>>(We, Woe, m2w1, m2w2, m1w1, m1w2, Won, Wq, Wk, Wv);
    node_pre_kernel<<<BAT*NTOK/16, 512>>>(x, bq, bk, bv, ln1s, ln1b);
    edge_kernel<<<BAT*NTOK, 512, smem>>>(y, be, boe, m2b1, m2b2,
                                         ln4s, ln4b, ln6s, ln6b, yout);
    node_post_kernel<<<BAT*NTOK/16, 512>>>(bon, m1b1, m1b2,
                                           ln3s, ln3b, ln5s, ln5b, xout);
}

// round 16
// speedup vs baseline: 1.0283x; 1.0283x over previous
#include <cuda_runtime.h>
#include <cuda_fp16.h>
#include <math.h>
#include <stdint.h>

#define DIMC 256
#define NTOK 128
#define BAT  8
#define HID  1024
#define EPSV 1e-5f
#define ASCALE 0.17677669529663687f

#define LDAh 264    // sAh row stride (halfs)
#define LDHh 136    // sHh row stride (halfs)
#define LDBh 72     // B chunk row stride (halfs)
#define KCH  64     // k per chunk (halfs)
#define BUFSZ  18432 // bytes per B buffer (edge: 128 rows)
#define BUFSZ2 36864 // bytes per B buffer (node: 256 rows)

// -------- device scratch --------
__device__ float g_x1 [BAT*NTOK*DIMC];
__device__ float g_q  [BAT*NTOK*DIMC];
__device__ float g_k  [BAT*NTOK*DIMC];
__device__ float g_v  [BAT*NTOK*DIMC];
__device__ float g_agg[BAT*NTOK*DIMC];
__device__ __half g_WeH [DIMC*DIMC];    // edge We   [n=256][k=256]
__device__ __half g_WoeH[DIMC*DIMC];    // edge Woe  [n=256][k=256]
__device__ __half g_W1H [HID*DIMC];     // EDGE mlp2_w1 [n=1024][k=256]
__device__ __half g_W2H [DIMC*HID];     // EDGE mlp2_w2 [n=256][k=1024]
__device__ __half g_N1H [HID*DIMC];     // NODE mlp1_w1 [n=1024][k=256]
__device__ __half g_N2H [DIMC*HID];     // NODE mlp1_w2 [n=256][k=1024]
__device__ __half g_WonH[DIMC*DIMC];    // Won [n=256][k=256]
__device__ __half g_QKVH[3*DIMC*DIMC];  // [n=768][k=256] (q,k,v stacked)

// -------- PTX helpers --------
__device__ __forceinline__ void mma16(float* d, const uint32_t* a, const uint32_t* b){
    asm volatile("mma.sync.aligned.m16n8k16.row.col.f32.f16.f16.f32 "
        "{%0,%1,%2,%3},{%4,%5,%6,%7},{%8,%9},{%0,%1,%2,%3};"
        : "+f"(d[0]),"+f"(d[1]),"+f"(d[2]),"+f"(d[3])
        : "r"(a[0]),"r"(a[1]),"r"(a[2]),"r"(a[3]),"r"(b[0]),"r"(b[1]));
}
__device__ __forceinline__ void ldsm4(uint32_t* r, uint32_t addr){
    asm volatile("ldmatrix.sync.aligned.m8n8.x4.shared.b16 {%0,%1,%2,%3}, [%4];"
        : "=r"(r[0]),"=r"(r[1]),"=r"(r[2]),"=r"(r[3]) : "r"(addr));
}
__device__ __forceinline__ void cpa16(uint32_t dst, const void* src){
    asm volatile("cp.async.cg.shared.global [%0], [%1], 16;" :: "r"(dst), "l"(src));
}
#define CP_COMMIT() asm volatile("cp.async.commit_group;" ::: "memory")
#define CP_WAIT(n)  asm volatile("cp.async.wait_group %0;" :: "n"(n) : "memory")

#define ZEROC(c, MF, NF) { _Pragma("unroll") for (int _m=0;_m<MF;_m++) _Pragma("unroll") for (int _n=0;_n<NF;_n++) _Pragma("unroll") for (int _u=0;_u<4;_u++) (c)[_m][_n][_u]=0.f; }

// ===== edge GEMM: 128-row A, 512 thr, 2-deep cp.async ring (unchanged) =====
__device__ __forceinline__ void gemm_h(
    uint32_t aLane, int ldah,
    const __half* __restrict__ gB, int ldgb, int k0, int nkc,
    uint32_t sB_u, uint32_t bLane,
    float c[2][4][4], int tid)
{
    const __half* src0 = gB + k0;
    #define STAGE(kc, s) { \
        const __half* _s = src0 + (kc)*KCH; \
        uint32_t _d = sB_u + (uint32_t)(s)*BUFSZ; \
        _Pragma("unroll") \
        for (int _j = 0; _j < 2; _j++){ \
            int _ii = tid + _j*512; \
            int _n = _ii >> 3, _q = _ii & 7; \
            cpa16(_d + (uint32_t)(_n*LDBh + _q*8)*2, _s + (size_t)_n*ldgb + _q*8); \
        } \
        CP_COMMIT(); }
    STAGE(0, 0);
    for (int kc = 0; kc < nkc; kc++){
        __syncthreads();
        if (kc + 1 < nkc){ STAGE(kc+1, (kc+1)&1); CP_WAIT(1); }
        else             { CP_WAIT(0); }
        __syncthreads();
        uint32_t bBuf = bLane + (uint32_t)(kc & 1)*BUFSZ;
        #pragma unroll
        for (int ks = 0; ks < KCH/16; ks++){
            uint32_t a[2][4];
            #pragma unroll
            for (int mf = 0; mf < 2; mf++)
                ldsm4(a[mf], aLane + (uint32_t)(mf*16*ldah + kc*KCH + ks*16)*2);
            #pragma unroll
            for (int np = 0; np < 2; np++){
                uint32_t b4[4];
                ldsm4(b4, bBuf + (uint32_t)(np*16*LDBh + ks*16)*2);
                uint32_t bx[2] = { b4[0], b4[2] };
                uint32_t by[2] = { b4[1], b4[3] };
                #pragma unroll
                for (int mf = 0; mf < 2; mf++){
                    mma16(c[mf][2*np+0], a[mf], bx);
                    mma16(c[mf][2*np+1], a[mf], by);
                }
            }
        }
    }
    #undef STAGE
}

// ===== node GEMM: 16-row A resident, B staged via cp.async ring =====
// NF=2: B panel 256 n-rows, warp covers 16 cols. NF=1: 128 n-rows, 8 cols.
template<int NF>
__device__ __forceinline__ void gemm16(
    uint32_t aLane, int lda,
    const __half* __restrict__ gB, int ldgb, int k0, int nkc,
    uint32_t sB_u, uint32_t bLane,
    float c[NF][4], int tid)
{
    const __half* src0 = gB + k0;
    #define STG(kc, s) { \
        const __half* _s = src0 + (kc)*KCH; \
        uint32_t _d = sB_u + (uint32_t)(s)*BUFSZ2; \
        _Pragma("unroll") \
        for (int _j = 0; _j < 2*NF; _j++){ \
            int _ii = tid + _j*512; \
            int _n = _ii >> 3, _q = _ii & 7; \
            cpa16(_d + (uint32_t)(_n*LDBh + _q*8)*2, _s + (size_t)_n*ldgb + _q*8); \
        } \
        CP_COMMIT(); }
    STG(0, 0);
    for (int kc = 0; kc < nkc; kc++){
        __syncthreads();
        if (kc + 1 < nkc){ STG(kc+1, (kc+1)&1); CP_WAIT(1); }
        else             { CP_WAIT(0); }
        __syncthreads();
        uint32_t bBuf = bLane + (uint32_t)(kc & 1)*BUFSZ2;
        #pragma unroll
        for (int ks = 0; ks < KCH/16; ks++){
            uint32_t a[4];
            ldsm4(a, aLane + (uint32_t)(kc*KCH + ks*16)*2);
            uint32_t b4[4];
            ldsm4(b4, bBuf + (uint32_t)(ks*16)*2);
            uint32_t bx[2] = { b4[0], b4[2] };
            mma16(c[0], a, bx);
            if (NF == 2){
                uint32_t by[2] = { b4[1], b4[3] };
                mma16(c[1], a, by);
            }
        }
    }
    #undef STG
}

// ================= prep: transpose + fp16 weights =================
__global__ __launch_bounds__(256) void prep_kernel(
    const float* __restrict__ We, const float* __restrict__ Woe,
    const float* __restrict__ w1, const float* __restrict__ w2,
    const float* __restrict__ n1, const float* __restrict__ n2,
    const float* __restrict__ Won,
    const float* __restrict__ Wq, const float* __restrict__ Wk,
    const float* __restrict__ Wv)
{
    int idx = blockIdx.x*256 + threadIdx.x;   // 0..262143
    if (idx < DIMC*DIMC){
        int n = idx >> 8, k = idx & 255;
        g_WeH [idx] = __float2half_rn(We [k*DIMC + n]);
        g_WoeH[idx] = __float2half_rn(Woe[k*DIMC + n]);
        g_WonH[idx] = __float2half_rn(Won[k*DIMC + n]);
    }
    {   int n = idx >> 8, k = idx & 255;
        g_W1H[idx] = __float2half_rn(w1[(size_t)k*HID + n]);
        g_N1H[idx] = __float2half_rn(n1[(size_t)k*HID + n]); }
    {   int n = idx >> 10, k = idx & 1023;
        g_W2H[idx] = __float2half_rn(w2[(size_t)k*DIMC + n]);
        g_N2H[idx] = __float2half_rn(n2[(size_t)k*DIMC + n]); }
    if (idx < 3*DIMC*DIMC){
        int n = idx >> 8, k = idx & 255;
        int mat = n >> 8, col = n & 255;
        const float* W = (mat == 0) ? Wq : (mat == 1) ? Wk : Wv;
        g_QKVH[idx] = __float2half_rn(W[k*DIMC + col]);
    }
}

// ================= kernel 1: LN1 + q/k/v (16 rows/CTA, staged B) =================
__global__ __launch_bounds__(512, 1) void node_pre_kernel(
    const float* __restrict__ x,
    const float* __restrict__ bq, const float* __restrict__ bk,
    const float* __restrict__ bv,
    const float* __restrict__ ln1s, const float* __restrict__ ln1b)
{
    extern __shared__ char smp[];
    __half* sA = (__half*)smp;                     // 16*264*2 = 8448
    uint32_t sB_u = (uint32_t)__cvta_generic_to_shared(smp + 8448);   // ring 2*36864
    uint32_t sA_u = (uint32_t)__cvta_generic_to_shared(sA);

    int tid = threadIdx.x, lane = tid & 31, w = tid >> 5;   // 16 warps
    int r0 = blockIdx.x * 16;
    int sub = lane >> 3, rin = lane & 7;

    // LN1: warp w -> row r0+w
    {
        const float* xr = x + (size_t)(r0 + w) * DIMC;
        float vals[8], s = 0.f, sq = 0.f;
        #pragma unroll
        for (int u = 0; u < 8; u++){ vals[u] = xr[lane + u*32]; s += vals[u]; sq += vals[u]*vals[u]; }
        #pragma unroll
        for (int o = 16; o > 0; o >>= 1){ s += __shfl_xor_sync(~0u,s,o); sq += __shfl_xor_sync(~0u,sq,o); }
        float mean = s * (1.f/DIMC);
        float rstd = rsqrtf(sq*(1.f/DIMC) - mean*mean + EPSV);
        #pragma unroll
        for (int u = 0; u < 8; u++){
            int c = lane + u*32;
            float v = (vals[u]-mean)*rstd*ln1s[c] + ln1b[c];
            g_x1[(r0+w)*DIMC + c] = v;
            sA[w*LDAh + c] = __float2half_rn(v);
        }
    }
    __syncthreads();

    uint32_t aLane = sA_u + (uint32_t)((((sub&1)*8 + rin)*LDAh + (sub>>1)*8)*2);
    uint32_t bLane = sB_u + (uint32_t)(((w*16 + (sub&1)*8 + rin)*LDBh + (sub>>1)*8)*2);
    int g = lane >> 2, t2 = (lane & 3)*2;

    #pragma unroll
    for (int pass = 0; pass < 3; pass++){
        float c[2][4];
        #pragma unroll
        for (int nf = 0; nf < 2; nf++)
            #pragma unroll
            for (int u = 0; u < 4; u++) c[nf][u] = 0.f;
        gemm16<2>(aLane, LDAh, g_QKVH + (size_t)pass*256*DIMC, DIMC, 0, 4, sB_u, bLane, c, tid);
        const float* bias = (pass == 0) ? bq : (pass == 1) ? bk : bv;
        float* dst = (pass == 0) ? g_q : (pass == 1) ? g_k : g_v;
        #pragma unroll
        for (int nf = 0; nf < 2; nf++){
            int col = w*16 + nf*8 + t2;
            *(float2*)(dst + (size_t)(r0+g)*DIMC + col) =
                make_float2(c[nf][0] + bias[col], c[nf][1] + bias[col+1]);
            *(float2*)(dst + (size_t)(r0+g+8)*DIMC + col) =
                make_float2(c[nf][2] + bias[col], c[nf][3] + bias[col+1]);
        }
    }
}

// ================= kernel 2: edge mega-kernel (fp16 mma, fp32 residuals) =================
__global__ __launch_bounds__(512, 1) void edge_kernel(
    const float* __restrict__ y,
    const float* __restrict__ be,  const float* __restrict__ boe,
    const float* __restrict__ b1,  const float* __restrict__ b2,
    const float* __restrict__ ln4s, const float* __restrict__ ln4b,
    const float* __restrict__ ln6s, const float* __restrict__ ln6b,
    float* __restrict__ yout)
{
    extern __shared__ char smem[];
    __half* sAh = (__half*)smem;                    // 67584
    __half* sRh = (__half*)(smem + 67584);          // 67584
    __half* sHh = (__half*)(smem + 135168);         // 34816
    char*   sBc = smem + 169984;                    // 36864
    float*  sS  = (float*)(smem + 206848);          // 512 f
    float*  sAg = (float*)(smem + 208896);          // 512 f
    float*  sQ  = (float*)(smem + 210944);          // 256 f

    uint32_t sA_u = (uint32_t)__cvta_generic_to_shared(sAh);
    uint32_t sH_u = (uint32_t)__cvta_generic_to_shared(sHh);
    uint32_t sB_u = (uint32_t)__cvta_generic_to_shared(sBc);

    int tid = threadIdx.x, lane = tid & 31, w = tid >> 5;
    int wm = (w >> 2) * 32, wn = w & 3;
    int g = lane >> 2, t = lane & 3;
    int sub = lane >> 3, rin = lane & 7;
    int bi = blockIdx.x, b = bi >> 7;
    const float* yblk = y + (size_t)bi * NTOK * DIMC;

    uint32_t aLaneA = sA_u + (uint32_t)(((wm + (sub&1)*8 + rin)*LDAh + (sub>>1)*8)*2);
    uint32_t aLaneH = sH_u + (uint32_t)(((wm + (sub&1)*8 + rin)*LDHh + (sub>>1)*8)*2);
    uint32_t bLane  = sB_u + (uint32_t)(((wn*32 + (sub&1)*8 + rin)*LDBh + (sub>>1)*8)*2);

    if (tid < 256) sQ[tid] = g_q[bi*DIMC + tid] * ASCALE;
    {
        const float4* y4 = (const float4*)yblk;
        for (int i = tid; i < 8192; i += 512){
            int r = i >> 6, kq = (i & 63) << 2;
            float4 v = y4[i];
            __half2* d = (__half2*)(sAh + r*LDAh + kq);
            d[0] = __floats2half2_rn(v.x, v.y);
            d[1] = __floats2half2_rn(v.z, v.w);
        }
    }

    float cE0[2][4][4], cE1[2][4][4];

    // ---- GEMM1: e = y @ We ----
    ZEROC(cE0, 2, 4); ZEROC(cE1, 2, 4);
    gemm_h(aLaneA, LDAh, g_WeH,            DIMC, 0, 4, sB_u, bLane, cE0, tid);
    gemm_h(aLaneA, LDAh, g_WeH + 128*DIMC, DIMC, 0, 4, sB_u, bLane, cE1, tid);
    __syncthreads();
    #pragma unroll
    for (int nc = 0; nc < 2; nc++)
    #pragma unroll
    for (int mf = 0; mf < 2; mf++)
    #pragma unroll
    for (int nf = 0; nf < 4; nf++)
    #pragma unroll
    for (int hh = 0; hh < 2; hh++){
        float* cc = nc ? cE1[mf][nf] : cE0[mf][nf];
        int r = wm + mf*16 + g + hh*8;
        int col = nc*128 + wn*32 + nf*8 + 2*t;
        float e0 = cc[2*hh+0] + be[col];
        float e1 = cc[2*hh+1] + be[col+1];
        float2 kv = *(const float2*)(g_k + (size_t)(b*NTOK + r)*DIMC + col);
        float v0 = sQ[col]  *kv.x*(e0 + 1.f)*e0;
        float v1 = sQ[col+1]*kv.y*(e1 + 1.f)*e1;
        *(__half2*)(sAh + r*LDAh + col) = __floats2half2_rn(v0, v1);
    }
    __syncthreads();

    // ---- softmax over j + agg ----
    {
        int half_ = tid >> 8, c = tid & 255;
        int j0 = half_*64;
        float mx = -1e30f;
        for (int j = j0; j < j0+64; j++) mx = fmaxf(mx, __half2float(sAh[j*LDAh + c]));
        sS[tid] = mx;
        __syncthreads();
        float M = fmaxf(sS[c], sS[256 + c]);
        float s = 0.f, agv = 0.f;
        for (int j = j0; j < j0+64; j++){
            float p = __expf(__half2float(sAh[j*LDAh + c]) - M);
            s += p;
            agv += p * g_v[(size_t)(b*NTOK + j)*DIMC + c];
        }
        __syncthreads();
        sS[tid] = s; sAg[tid] = agv;
        __syncthreads();
        if (tid < 256)
            g_agg[bi*DIMC + tid] = (sAg[tid] + sAg[256+tid]) / (sS[tid] + sS[256+tid]);
        __syncthreads();
    }

    // ---- GEMM2: edge_out = attn @ Woe ----
    ZEROC(cE0, 2, 4); ZEROC(cE1, 2, 4);
    gemm_h(aLaneA, LDAh, g_WoeH,            DIMC, 0, 4, sB_u, bLane, cE0, tid);
    gemm_h(aLaneA, LDAh, g_WoeH + 128*DIMC, DIMC, 0, 4, sB_u, bLane, cE1, tid);

    // ---- epilogue2 + LN4 in fp32 registers ----
    {
        float ps[2][2] = {}, pq[2][2] = {};
        #pragma unroll
        for (int nc = 0; nc < 2; nc++)
        #pragma unroll
        for (int mf = 0; mf < 2; mf++)
        #pragma unroll
        for (int nf = 0; nf < 4; nf++)
        #pragma unroll
        for (int hh = 0; hh < 2; hh++){
            float* cc = nc ? cE1[mf][nf] : cE0[mf][nf];
            int r = wm + mf*16 + g + hh*8;
            int col = nc*128 + wn*32 + nf*8 + 2*t;
            float2 yv = *(const float2*)(yblk + (size_t)r*DIMC + col);
            float v0 = cc[2*hh+0] + boe[col]   + yv.x;
            float v1 = cc[2*hh+1] + boe[col+1] + yv.y;
            cc[2*hh+0] = v0; cc[2*hh+1] = v1;
            ps[mf][hh] += v0 + v1; pq[mf][hh] += v0*v0 + v1*v1;
        }
        #pragma unroll
        for (int mf = 0; mf < 2; mf++)
        #pragma unroll
        for (int hh = 0; hh < 2; hh++){
            ps[mf][hh] += __shfl_xor_sync(~0u, ps[mf][hh], 1);
            ps[mf][hh] += __shfl_xor_sync(~0u, ps[mf][hh], 2);
            pq[mf][hh] += __shfl_xor_sync(~0u, pq[mf][hh], 1);
            pq[mf][hh] += __shfl_xor_sync(~0u, pq[mf][hh], 2);
        }
        if (t == 0){
            #pragma unroll
            for (int mf = 0; mf < 2; mf++)
            #pragma unroll
            for (int hh = 0; hh < 2; hh++){
                int r = wm + mf*16 + g + hh*8;
                sS [wn*128 + r] = ps[mf][hh];
                sAg[wn*128 + r] = pq[mf][hh];
            }
        }
        __syncthreads();
        #pragma unroll
        for (int mf = 0; mf < 2; mf++)
        #pragma unroll
        for (int hh = 0; hh < 2; hh++){
            int r = wm + mf*16 + g + hh*8;
            float S = sS[r] + sS[128+r] + sS[256+r] + sS[384+r];
            float Q = sAg[r] + sAg[128+r] + sAg[256+r] + sAg[384+r];
            float mean = S * (1.f/256.f);
            float rstd = rsqrtf(Q*(1.f/256.f) - mean*mean + EPSV);
            #pragma unroll
            for (int nc = 0; nc < 2; nc++)
            #pragma unroll
            for (int nf = 0; nf < 4; nf++){
                float* cc = nc ? cE1[mf][nf] : cE0[mf][nf];
                int col = nc*128 + wn*32 + nf*8 + 2*t;
                float v0 = (cc[2*hh+0] - mean)*rstd*ln4s[col]   + ln4b[col];
                float v1 = (cc[2*hh+1] - mean)*rstd*ln4s[col+1] + ln4b[col+1];
                __half h0 = __float2half_rn(v0), h1 = __float2half_rn(v1);
                *(__half2*)(sAh + r*LDAh + col) = __halves2half2(h0, h1);
                *(__half2*)(sRh + r*LDAh + col) =
                    __floats2half2_rn(v0 - __half2float(h0), v1 - __half2float(h1));
            }
        }
    }

    // ---- MLP ----
    float cM0[2][4][4], cM1[2][4][4];
    ZEROC(cM0, 2, 4); ZEROC(cM1, 2, 4);
    for (int ht = 0; ht < 8; ht++){
        float cH[2][4][4];
        ZEROC(cH, 2, 4);
        gemm_h(aLaneA, LDAh, g_W1H + (size_t)ht*128*DIMC, DIMC, 0, 4, sB_u, bLane, cH, tid);
        #pragma unroll
        for (int mf = 0; mf < 2; mf++)
        #pragma unroll
        for (int nf = 0; nf < 4; nf++)
        #pragma unroll
        for (int hh = 0; hh < 2; hh++){
            int r = wm + mf*16 + g + hh*8;
            int col = wn*32 + nf*8 + 2*t;
            float h0 = fmaxf(cH[mf][nf][2*hh+0] + b1[ht*128 + col],     0.f);
            float h1 = fmaxf(cH[mf][nf][2*hh+1] + b1[ht*128 + col + 1], 0.f);
            *(__half2*)(sHh + r*LDHh + col) = __floats2half2_rn(h0, h1);
        }
        gemm_h(aLaneH, LDHh, g_W2H,                   HID, ht*128, 2, sB_u, bLane, cM0, tid);
        gemm_h(aLaneH, LDHh, g_W2H + (size_t)128*HID, HID, ht*128, 2, sB_u, bLane, cM1, tid);
    }

    // ---- LN6 -> yout ----
    {
        float ps[2][2] = {}, pq[2][2] = {};
        #pragma unroll
        for (int nc = 0; nc < 2; nc++)
        #pragma unroll
        for (int mf = 0; mf < 2; mf++)
        #pragma unroll
        for (int nf = 0; nf < 4; nf++)
        #pragma unroll
        for (int hh = 0; hh < 2; hh++){
            float* cc = nc ? cM1[mf][nf] : cM0[mf][nf];
            int r = wm + mf*16 + g + hh*8;
            int col = nc*128 + wn*32 + nf*8 + 2*t;
            float2 hi = __half22float2(*(__half2*)(sAh + r*LDAh + col));
            float2 lo = __half22float2(*(__half2*)(sRh + r*LDAh + col));
            float v0 = cc[2*hh+0] + b2[col]   + hi.x + lo.x;
            float v1 = cc[2*hh+1] + b2[col+1] + hi.y + lo.y;
            cc[2*hh+0] = v0; cc[2*hh+1] = v1;
            ps[mf][hh] += v0 + v1; pq[mf][hh] += v0*v0 + v1*v1;
        }
        #pragma unroll
        for (int mf = 0; mf < 2; mf++)
        #pragma unroll
        for (int hh = 0; hh < 2; hh++){
            ps[mf][hh] += __shfl_xor_sync(~0u, ps[mf][hh], 1);
            ps[mf][hh] += __shfl_xor_sync(~0u, ps[mf][hh], 2);
            pq[mf][hh] += __shfl_xor_sync(~0u, pq[mf][hh], 1);
            pq[mf][hh] += __shfl_xor_sync(~0u, pq[mf][hh], 2);
        }
        __syncthreads();
        if (t == 0){
            #pragma unroll
            for (int mf = 0; mf < 2; mf++)
            #pragma unroll
            for (int hh = 0; hh < 2; hh++){
                int r = wm + mf*16 + g + hh*8;
                sS [wn*128 + r] = ps[mf][hh];
                sAg[wn*128 + r] = pq[mf][hh];
            }
        }
        __syncthreads();
        float* youtb = yout + (size_t)bi*NTOK*DIMC;
        #pragma unroll
        for (int mf = 0; mf < 2; mf++)
        #pragma unroll
        for (int hh = 0; hh < 2; hh++){
            int r = wm + mf*16 + g + hh*8;
            float S = sS[r] + sS[128+r] + sS[256+r] + sS[384+r];
            float Q = sAg[r] + sAg[128+r] + sAg[256+r] + sAg[384+r];
            float mean = S * (1.f/256.f);
            float rstd = rsqrtf(Q*(1.f/256.f) - mean*mean + EPSV);
            #pragma unroll
            for (int nc = 0; nc < 2; nc++)
            #pragma unroll
            for (int nf = 0; nf < 4; nf++){
                float* cc = nc ? cM1[mf][nf] : cM0[mf][nf];
                int col = nc*128 + wn*32 + nf*8 + 2*t;
                float v0 = (cc[2*hh+0] - mean)*rstd*ln6s[col]   + ln6b[col];
                float v1 = (cc[2*hh+1] - mean)*rstd*ln6s[col+1] + ln6b[col+1];
                *(float2*)(youtb + (size_t)r*DIMC + col) = make_float2(v0, v1);
            }
        }
    }
}

// ================= kernel 3: node post (16 rows/CTA, staged B) =================
__global__ __launch_bounds__(512, 1) void node_post_kernel(
    const float* __restrict__ bon,
    const float* __restrict__ b1, const float* __restrict__ b2,
    const float* __restrict__ ln3s, const float* __restrict__ ln3b,
    const float* __restrict__ ln5s, const float* __restrict__ ln5b,
    float* __restrict__ xout)
{
    extern __shared__ char smp[];
    __half* sA = (__half*)smp;                         // 8448
    __half* sH = (__half*)(smp + 8448);                // 4352
    uint32_t sB_u = (uint32_t)__cvta_generic_to_shared(smp + 12800);  // 2*36864
    float* sX   = (float*)(smp + 86528);               // 16*260*4 = 16640
    float* sRed = (float*)(smp + 103168);              // 2*256*4 = 2048
    uint32_t sA_u = (uint32_t)__cvta_generic_to_shared(sA);
    uint32_t sH_u = (uint32_t)__cvta_generic_to_shared(sH);

    int tid = threadIdx.x, lane = tid & 31, w = tid >> 5;   // 16 warps
    int r0 = blockIdx.x * 16;
    int sub = lane >> 3, rin = lane & 7;
    int g = lane >> 2, t2 = (lane & 3)*2;

    for (int i = tid; i < 16*256; i += 512){
        int r = i >> 8, c = i & 255;
        sA[r*LDAh + c] = __float2half_rn(g_agg[(size_t)(r0+r)*DIMC + c]);
    }
    __syncthreads();

    uint32_t aLane  = sA_u + (uint32_t)((((sub&1)*8 + rin)*LDAh + (sub>>1)*8)*2);
    uint32_t hLane  = sH_u + (uint32_t)((((sub&1)*8 + rin)*LDHh + (sub>>1)*8)*2);
    uint32_t bLane16 = sB_u + (uint32_t)(((w*16 + (sub&1)*8 + rin)*LDBh + (sub>>1)*8)*2);
    uint32_t bLane8  = sB_u + (uint32_t)(((w*8  + (sub&1)*8 + rin)*LDBh + (sub>>1)*8)*2);

    // GEMM: x2pre = agg @ Won (staged B, NF=2)
    float c1[2][4];
    #pragma unroll
    for (int nf = 0; nf < 2; nf++)
        #pragma unroll
        for (int u = 0; u < 4; u++) c1[nf][u] = 0.f;
    gemm16<2>(aLane, LDAh, g_WonH, DIMC, 0, 4, sB_u, bLane16, c1, tid);

    // epilogue + LN3 (two row groups: g, g+8)
    {
        float v[2][4], ps[2] = {}, pq[2] = {};
        #pragma unroll
        for (int nf = 0; nf < 2; nf++){
            int col = w*16 + nf*8 + t2;
            float2 xA = *(const float2*)(g_x1 + (size_t)(r0+g)*DIMC + col);
            float2 xB = *(const float2*)(g_x1 + (size_t)(r0+g+8)*DIMC + col);
            v[nf][0] = c1[nf][0] + bon[col]   + xA.x;
            v[nf][1] = c1[nf][1] + bon[col+1] + xA.y;
            v[nf][2] = c1[nf][2] + bon[col]   + xB.x;
            v[nf][3] = c1[nf][3] + bon[col+1] + xB.y;
            ps[0] += v[nf][0] + v[nf][1]; pq[0] += v[nf][0]*v[nf][0] + v[nf][1]*v[nf][1];
            ps[1] += v[nf][2] + v[nf][3]; pq[1] += v[nf][2]*v[nf][2] + v[nf][3]*v[nf][3];
        }
        #pragma unroll
        for (int rg = 0; rg < 2; rg++){
            ps[rg] += __shfl_xor_sync(~0u, ps[rg], 1); pq[rg] += __shfl_xor_sync(~0u, pq[rg], 1);
            ps[rg] += __shfl_xor_sync(~0u, ps[rg], 2); pq[rg] += __shfl_xor_sync(~0u, pq[rg], 2);
        }
        if ((lane & 3) == 0){
            sRed[0*256 + w*16 + g]     = ps[0]; sRed[1*256 + w*16 + g]     = pq[0];
            sRed[0*256 + w*16 + g + 8] = ps[1]; sRed[1*256 + w*16 + g + 8] = pq[1];
        }
        __syncthreads();
        #pragma unroll
        for (int rg = 0; rg < 2; rg++){
            int rr = g + rg*8;
            float S = 0.f, Q = 0.f;
            #pragma unroll
            for (int ww = 0; ww < 16; ww++){ S += sRed[0*256 + ww*16 + rr]; Q += sRed[1*256 + ww*16 + rr]; }
            float mean = S * (1.f/256.f);
            float rstd = rsqrtf(Q*(1.f/256.f) - mean*mean + EPSV);
            #pragma unroll
            for (int nf = 0; nf < 2; nf++){
                int col = w*16 + nf*8 + t2;
                float x0 = (v[nf][2*rg+0] - mean)*rstd*ln3s[col]   + ln3b[col];
                float x1 = (v[nf][2*rg+1] - mean)*rstd*ln3s[col+1] + ln3b[col+1];
                sX[rr*260 + col] = x0; sX[rr*260 + col + 1] = x1;
                *(__half2*)(sA + rr*LDAh + col) = __floats2half2_rn(x0, x1);
            }
        }
        __syncthreads();
    }

    // MLP: ht-interleaved, staged B
    float cM[2][4];
    #pragma unroll
    for (int nf = 0; nf < 2; nf++)
        #pragma unroll
        for (int u = 0; u < 4; u++) cM[nf][u] = 0.f;
    for (int ht = 0; ht < 8; ht++){
        // MLP1: 128 hidden cols -> 16 warps x 8 (NF=1)
        float cH[1][4];
        #pragma unroll
        for (int u = 0; u < 4; u++) cH[0][u] = 0.f;
        gemm16<1>(aLane, LDAh, g_N1H + (size_t)ht*128*DIMC, DIMC, 0, 4, sB_u, bLane8, cH, tid);
        // write h tile (gemm16's internal sync guarantees all prev MLP2 reads done)
        {
            int col = w*8 + t2;
            *(__half2*)(sH + g*LDHh + col) = __floats2half2_rn(
                fmaxf(cH[0][0] + b1[ht*128 + col],     0.f),
                fmaxf(cH[0][1] + b1[ht*128 + col + 1], 0.f));
            *(__half2*)(sH + (g+8)*LDHh + col) = __floats2half2_rn(
                fmaxf(cH[0][2] + b1[ht*128 + col],     0.f),
                fmaxf(cH[0][3] + b1[ht*128 + col + 1], 0.f));
        }
        // MLP2: 256 out cols -> 16 warps x 16 (NF=2), k window ht*128 (2 chunks)
        // (gemm16's first internal __syncthreads orders the sH writes above)
        gemm16<2>(hLane, LDHh, g_N2H, HID, ht*128, 2, sB_u, bLane16, cM, tid);
    }

    // final: out = cM + b2 + x2 ; LN5 -> xout (two row groups)
    {
        float v[2][4], ps[2] = {}, pq[2] = {};
        #pragma unroll
        for (int nf = 0; nf < 2; nf++){
            int col = w*16 + nf*8 + t2;
            v[nf][0] = cM[nf][0] + b2[col]   + sX[g*260 + col];
            v[nf][1] = cM[nf][1] + b2[col+1] + sX[g*260 + col + 1];
            v[nf][2] = cM[nf][2] + b2[col]   + sX[(g+8)*260 + col];
            v[nf][3] = cM[nf][3] + b2[col+1] + sX[(g+8)*260 + col + 1];
            ps[0] += v[nf][0] + v[nf][1]; pq[0] += v[nf][0]*v[nf][0] + v[nf][1]*v[nf][1];
            ps[1] += v[nf][2] + v[nf][3]; pq[1] += v[nf][2]*v[nf][2] + v[nf][3]*v[nf][3];
        }
        #pragma unroll
        for (int rg = 0; rg < 2; rg++){
            ps[rg] += __shfl_xor_sync(~0u, ps[rg], 1); pq[rg] += __shfl_xor_sync(~0u, pq[rg], 1);
            ps[rg] += __shfl_xor_sync(~0u, ps[rg], 2); pq[rg] += __shfl_xor_sync(~0u, pq[rg], 2);
        }
        __syncthreads();
        if ((lane & 3) == 0){
            sRed[0*256 + w*16 + g]     = ps[0]; sRed[1*256 + w*16 + g]     = pq[0];
            sRed[0*256 + w*16 + g + 8] = ps[1]; sRed[1*256 + w*16 + g + 8] = pq[1];
        }
        __syncthreads();
        #pragma unroll
        for (int rg = 0; rg < 2; rg++){
            int rr = g + rg*8;
            float S = 0.f, Q = 0.f;
            #pragma unroll
            for (int ww = 0; ww < 16; ww++){ S += sRed[0*256 + ww*16 + rr]; Q += sRed[1*256 + ww*16 + rr]; }
            float mean = S * (1.f/256.f);
            float rstd = rsqrtf(Q*(1.f/256.f) - mean*mean + EPSV);
            #pragma unroll
            for (int nf = 0; nf < 2; nf++){
                int col = w*16 + nf*8 + t2;
                float o0 = (v[nf][2*rg+0] - mean)*rstd*ln5s[col]   + ln5b[col];
                float o1 = (v[nf][2*rg+1] - mean)*rstd*ln5s[col+1] + ln5b[col+1];
                *(float2*)(xout + (size_t)(r0+rr)*DIMC + col) = make_float2(o0, o1);
            }
        }
    }
}

// ================= launch =================
extern "C" void kernel_launch(void* const* d_in, const int* in_sizes, int n_in,
                              void* d_out, int out_size)
{
    const float* x    = (const float*)d_in[0];
    const float* y    = (const float*)d_in[1];
    const float* Wq   = (const float*)d_in[2];  const float* bq  = (const float*)d_in[3];
    const float* Wk   = (const float*)d_in[4];  const float* bk  = (const float*)d_in[5];
    const float* Wv   = (const float*)d_in[6];  const float* bv  = (const float*)d_in[7];
    const float* We   = (const float*)d_in[8];  const float* be  = (const float*)d_in[9];
    const float* Woe  = (const float*)d_in[10]; const float* boe = (const float*)d_in[11];
    const float* Won  = (const float*)d_in[12]; const float* bon = (const float*)d_in[13];
    const float* m1w1 = (const float*)d_in[14]; const float* m1b1= (const float*)d_in[15];
    const float* m1w2 = (const float*)d_in[16]; const float* m1b2= (const float*)d_in[17];
    const float* m2w1 = (const float*)d_in[18]; const float* m2b1= (const float*)d_in[19];
    const float* m2w2 = (const float*)d_in[20]; const float* m2b2= (const float*)d_in[21];
    const float* ln1s = (const float*)d_in[22]; const float* ln1b= (const float*)d_in[23];
    const float* ln3s = (const float*)d_in[24]; const float* ln3b= (const float*)d_in[25];
    const float* ln4s = (const float*)d_in[26]; const float* ln4b= (const float*)d_in[27];
    const float* ln5s = (const float*)d_in[28]; const float* ln5b= (const float*)d_in[29];
    const float* ln6s = (const float*)d_in[30]; const float* ln6b= (const float*)d_in[31];

    float* out  = (float*)d_out;
    float* xout = out;                               // (8,128,256)
    float* yout = out + BAT*NTOK*DIMC;               // (8,128,128,256)

    int smemE = 211968;
    int smemPre  = 8448 + 2*BUFSZ2;                  // 82176
    int smemPost = 103168 + 2048;                    // 105216
    cudaFuncSetAttribute(edge_kernel, cudaFuncAttributeMaxDynamicSharedMemorySize, smemE);
    cudaFuncSetAttribute(node_pre_kernel, cudaFuncAttributeMaxDynamicSharedMemorySize, smemPre);
    cudaFuncSetAttribute(node_post_kernel, cudaFuncAttributeMaxDynamicSharedMemorySize, smemPost);

    prep_kernel<<<1024, 256>>>(We, Woe, m2w1, m2w2, m1w1, m1w2, Won, Wq, Wk, Wv);
    node_pre_kernel<<<BAT*NTOK/16, 512, smemPre>>>(x, bq, bk, bv, ln1s, ln1b);
    edge_kernel<<<BAT*NTOK, 512, smemE>>>(y, be, boe, m2b1, m2b2,
                                          ln4s, ln4b, ln6s, ln6b, yout);
    node_post_kernel<<<BAT*NTOK/16, 512, smemPost>>>(bon, m1b1, m1b2,
                                                     ln3s, ln3b, ln5s, ln5b, xout);
}

// round 17
// speedup vs baseline: 1.0322x; 1.0039x over previous
#include <cuda_runtime.h>
#include <cuda_fp16.h>
#include <math.h>
#include <stdint.h>

#define DIMC 256
#define NTOK 128
#define BAT  8
#define HID  1024
#define EPSV 1e-5f
#define ASCALE 0.17677669529663687f

#define LDAh 264    // sAh row stride (halfs)
#define LDHh 136    // edge sHh row stride (halfs)
#define LDH2 1032   // node_post full h row stride (halfs)
#define LDBh 72     // B chunk row stride (halfs)
#define KCH  64     // k per chunk (halfs)
#define BUFSZ  18432 // bytes per B buffer (edge: 128 rows)
#define BUFSZ2 36864 // bytes per B buffer (node: 256 rows)

// -------- device scratch --------
__device__ float g_x1 [BAT*NTOK*DIMC];
__device__ float g_q  [BAT*NTOK*DIMC];
__device__ float g_k  [BAT*NTOK*DIMC];
__device__ float g_v  [BAT*NTOK*DIMC];
__device__ float g_agg[BAT*NTOK*DIMC];
__device__ __half g_WeH [DIMC*DIMC];    // edge We   [n=256][k=256]
__device__ __half g_WoeH[DIMC*DIMC];    // edge Woe  [n=256][k=256]
__device__ __half g_W1H [HID*DIMC];     // EDGE mlp2_w1 [n=1024][k=256]
__device__ __half g_W2H [DIMC*HID];     // EDGE mlp2_w2 [n=256][k=1024]
__device__ __half g_N1H [HID*DIMC];     // NODE mlp1_w1 [n=1024][k=256]
__device__ __half g_N2H [DIMC*HID];     // NODE mlp1_w2 [n=256][k=1024]
__device__ __half g_WonH[DIMC*DIMC];    // Won [n=256][k=256]
__device__ __half g_QKVH[3*DIMC*DIMC];  // [n=768][k=256] (q,k,v stacked)

// -------- PTX helpers --------
__device__ __forceinline__ void mma16(float* d, const uint32_t* a, const uint32_t* b){
    asm volatile("mma.sync.aligned.m16n8k16.row.col.f32.f16.f16.f32 "
        "{%0,%1,%2,%3},{%4,%5,%6,%7},{%8,%9},{%0,%1,%2,%3};"
        : "+f"(d[0]),"+f"(d[1]),"+f"(d[2]),"+f"(d[3])
        : "r"(a[0]),"r"(a[1]),"r"(a[2]),"r"(a[3]),"r"(b[0]),"r"(b[1]));
}
__device__ __forceinline__ void ldsm4(uint32_t* r, uint32_t addr){
    asm volatile("ldmatrix.sync.aligned.m8n8.x4.shared.b16 {%0,%1,%2,%3}, [%4];"
        : "=r"(r[0]),"=r"(r[1]),"=r"(r[2]),"=r"(r[3]) : "r"(addr));
}
__device__ __forceinline__ void cpa16(uint32_t dst, const void* src){
    asm volatile("cp.async.cg.shared.global [%0], [%1], 16;" :: "r"(dst), "l"(src));
}
#define CP_COMMIT() asm volatile("cp.async.commit_group;" ::: "memory")
#define CP_WAIT(n)  asm volatile("cp.async.wait_group %0;" :: "n"(n) : "memory")

#define ZEROC(c, MF, NF) { _Pragma("unroll") for (int _m=0;_m<MF;_m++) _Pragma("unroll") for (int _n=0;_n<NF;_n++) _Pragma("unroll") for (int _u=0;_u<4;_u++) (c)[_m][_n][_u]=0.f; }

// ===== edge GEMM: 128-row A, 512 thr, 2-deep cp.async ring (unchanged) =====
__device__ __forceinline__ void gemm_h(
    uint32_t aLane, int ldah,
    const __half* __restrict__ gB, int ldgb, int k0, int nkc,
    uint32_t sB_u, uint32_t bLane,
    float c[2][4][4], int tid)
{
    const __half* src0 = gB + k0;
    #define STAGE(kc, s) { \
        const __half* _s = src0 + (kc)*KCH; \
        uint32_t _d = sB_u + (uint32_t)(s)*BUFSZ; \
        _Pragma("unroll") \
        for (int _j = 0; _j < 2; _j++){ \
            int _ii = tid + _j*512; \
            int _n = _ii >> 3, _q = _ii & 7; \
            cpa16(_d + (uint32_t)(_n*LDBh + _q*8)*2, _s + (size_t)_n*ldgb + _q*8); \
        } \
        CP_COMMIT(); }
    STAGE(0, 0);
    for (int kc = 0; kc < nkc; kc++){
        __syncthreads();
        if (kc + 1 < nkc){ STAGE(kc+1, (kc+1)&1); CP_WAIT(1); }
        else             { CP_WAIT(0); }
        __syncthreads();
        uint32_t bBuf = bLane + (uint32_t)(kc & 1)*BUFSZ;
        #pragma unroll
        for (int ks = 0; ks < KCH/16; ks++){
            uint32_t a[2][4];
            #pragma unroll
            for (int mf = 0; mf < 2; mf++)
                ldsm4(a[mf], aLane + (uint32_t)(mf*16*ldah + kc*KCH + ks*16)*2);
            #pragma unroll
            for (int np = 0; np < 2; np++){
                uint32_t b4[4];
                ldsm4(b4, bBuf + (uint32_t)(np*16*LDBh + ks*16)*2);
                uint32_t bx[2] = { b4[0], b4[2] };
                uint32_t by[2] = { b4[1], b4[3] };
                #pragma unroll
                for (int mf = 0; mf < 2; mf++){
                    mma16(c[mf][2*np+0], a[mf], bx);
                    mma16(c[mf][2*np+1], a[mf], by);
                }
            }
        }
    }
    #undef STAGE
}

// ===== node GEMM: 16-row A resident, B staged via cp.async ring (single call) =====
template<int NF>
__device__ __forceinline__ void gemm16(
    uint32_t aLane, int lda,
    const __half* __restrict__ gB, int ldgb, int k0, int nkc,
    uint32_t sB_u, uint32_t bLane,
    float c[NF][4], int tid)
{
    const __half* src0 = gB + k0;
    #define STG(kc, s) { \
        const __half* _s = src0 + (kc)*KCH; \
        uint32_t _d = sB_u + (uint32_t)(s)*BUFSZ2; \
        _Pragma("unroll") \
        for (int _j = 0; _j < 2*NF; _j++){ \
            int _ii = tid + _j*512; \
            int _n = _ii >> 3, _q = _ii & 7; \
            cpa16(_d + (uint32_t)(_n*LDBh + _q*8)*2, _s + (size_t)_n*ldgb + _q*8); \
        } \
        CP_COMMIT(); }
    STG(0, 0);
    for (int kc = 0; kc < nkc; kc++){
        __syncthreads();
        if (kc + 1 < nkc){ STG(kc+1, (kc+1)&1); CP_WAIT(1); }
        else             { CP_WAIT(0); }
        __syncthreads();
        uint32_t bBuf = bLane + (uint32_t)(kc & 1)*BUFSZ2;
        #pragma unroll
        for (int ks = 0; ks < KCH/16; ks++){
            uint32_t a[4];
            ldsm4(a, aLane + (uint32_t)((k0 % 0x40000000, kc*KCH + ks*16))*2);
            uint32_t b4[4];
            ldsm4(b4, bBuf + (uint32_t)(ks*16)*2);
            uint32_t bx[2] = { b4[0], b4[2] };
            mma16(c[0], a, bx);
            if (NF == 2){
                uint32_t by[2] = { b4[1], b4[3] };
                mma16(c[1], a, by);
            }
        }
    }
    #undef STG
}

// ================= prep: transpose + fp16 weights =================
__global__ __launch_bounds__(256) void prep_kernel(
    const float* __restrict__ We, const float* __restrict__ Woe,
    const float* __restrict__ w1, const float* __restrict__ w2,
    const float* __restrict__ n1, const float* __restrict__ n2,
    const float* __restrict__ Won,
    const float* __restrict__ Wq, const float* __restrict__ Wk,
    const float* __restrict__ Wv)
{
    int idx = blockIdx.x*256 + threadIdx.x;   // 0..262143
    if (idx < DIMC*DIMC){
        int n = idx >> 8, k = idx & 255;
        g_WeH [idx] = __float2half_rn(We [k*DIMC + n]);
        g_WoeH[idx] = __float2half_rn(Woe[k*DIMC + n]);
        g_WonH[idx] = __float2half_rn(Won[k*DIMC + n]);
    }
    {   int n = idx >> 8, k = idx & 255;
        g_W1H[idx] = __float2half_rn(w1[(size_t)k*HID + n]);
        g_N1H[idx] = __float2half_rn(n1[(size_t)k*HID + n]); }
    {   int n = idx >> 10, k = idx & 1023;
        g_W2H[idx] = __float2half_rn(w2[(size_t)k*DIMC + n]);
        g_N2H[idx] = __float2half_rn(n2[(size_t)k*DIMC + n]); }
    if (idx < 3*DIMC*DIMC){
        int n = idx >> 8, k = idx & 255;
        int mat = n >> 8, col = n & 255;
        const float* W = (mat == 0) ? Wq : (mat == 1) ? Wk : Wv;
        g_QKVH[idx] = __float2half_rn(W[k*DIMC + col]);
    }
}

// ================= kernel 1: LN1 + q/k/v (16 rows/CTA, fused 12-chunk ring) =================
__global__ __launch_bounds__(512, 1) void node_pre_kernel(
    const float* __restrict__ x,
    const float* __restrict__ bq, const float* __restrict__ bk,
    const float* __restrict__ bv,
    const float* __restrict__ ln1s, const float* __restrict__ ln1b)
{
    extern __shared__ char smp[];
    __half* sA = (__half*)smp;                     // 8448
    uint32_t sB_u = (uint32_t)__cvta_generic_to_shared(smp + 8448);   // ring 2*36864
    uint32_t sA_u = (uint32_t)__cvta_generic_to_shared(sA);

    int tid = threadIdx.x, lane = tid & 31, w = tid >> 5;   // 16 warps
    int r0 = blockIdx.x * 16;
    int sub = lane >> 3, rin = lane & 7;

    // LN1: warp w -> row r0+w
    {
        const float* xr = x + (size_t)(r0 + w) * DIMC;
        float vals[8], s = 0.f, sq = 0.f;
        #pragma unroll
        for (int u = 0; u < 8; u++){ vals[u] = xr[lane + u*32]; s += vals[u]; sq += vals[u]*vals[u]; }
        #pragma unroll
        for (int o = 16; o > 0; o >>= 1){ s += __shfl_xor_sync(~0u,s,o); sq += __shfl_xor_sync(~0u,sq,o); }
        float mean = s * (1.f/DIMC);
        float rstd = rsqrtf(sq*(1.f/DIMC) - mean*mean + EPSV);
        #pragma unroll
        for (int u = 0; u < 8; u++){
            int c = lane + u*32;
            float v = (vals[u]-mean)*rstd*ln1s[c] + ln1b[c];
            g_x1[(r0+w)*DIMC + c] = v;
            sA[w*LDAh + c] = __float2half_rn(v);
        }
    }
    __syncthreads();

    uint32_t aLane = sA_u + (uint32_t)((((sub&1)*8 + rin)*LDAh + (sub>>1)*8)*2);
    uint32_t bLane = sB_u + (uint32_t)(((w*16 + (sub&1)*8 + rin)*LDBh + (sub>>1)*8)*2);
    int g = lane >> 2, t2 = (lane & 3)*2;

    // fused QKV: 3 panels x 4 chunks, continuous 2-deep ring
    #define STGQ(ci) { \
        int _p = (ci) >> 2, _kc = (ci) & 3; \
        const __half* _s = g_QKVH + (size_t)(_p*256)*DIMC + _kc*KCH; \
        uint32_t _d = sB_u + (uint32_t)((ci)&1)*BUFSZ2; \
        _Pragma("unroll") \
        for (int _j = 0; _j < 4; _j++){ \
            int _ii = tid + _j*512; \
            int _n = _ii >> 3, _q = _ii & 7; \
            cpa16(_d + (uint32_t)(_n*LDBh + _q*8)*2, _s + (size_t)_n*DIMC + _q*8); \
        } \
        CP_COMMIT(); }
    float c[2][4];
    #pragma unroll
    for (int nf = 0; nf < 2; nf++)
        #pragma unroll
        for (int u = 0; u < 4; u++) c[nf][u] = 0.f;
    STGQ(0);
    for (int ci = 0; ci < 12; ci++){
        int kc = ci & 3, p = ci >> 2;
        __syncthreads();
        if (ci + 1 < 12){ STGQ(ci+1); CP_WAIT(1); }
        else            { CP_WAIT(0); }
        __syncthreads();
        uint32_t bBuf = bLane + (uint32_t)(ci & 1)*BUFSZ2;
        #pragma unroll
        for (int ks = 0; ks < 4; ks++){
            uint32_t a[4];
            ldsm4(a, aLane + (uint32_t)((kc*KCH + ks*16))*2);
            uint32_t b4[4];
            ldsm4(b4, bBuf + (uint32_t)(ks*16)*2);
            uint32_t bx[2] = { b4[0], b4[2] };
            uint32_t by[2] = { b4[1], b4[3] };
            mma16(c[0], a, bx);
            mma16(c[1], a, by);
        }
        if (kc == 3){
            const float* bias = (p == 0) ? bq : (p == 1) ? bk : bv;
            float* dst = (p == 0) ? g_q : (p == 1) ? g_k : g_v;
            #pragma unroll
            for (int nf = 0; nf < 2; nf++){
                int col = w*16 + nf*8 + t2;
                *(float2*)(dst + (size_t)(r0+g)*DIMC + col) =
                    make_float2(c[nf][0] + bias[col], c[nf][1] + bias[col+1]);
                *(float2*)(dst + (size_t)(r0+g+8)*DIMC + col) =
                    make_float2(c[nf][2] + bias[col], c[nf][3] + bias[col+1]);
                #pragma unroll
                for (int u = 0; u < 4; u++) c[nf][u] = 0.f;
            }
        }
    }
    #undef STGQ
}

// ================= kernel 2: edge mega-kernel (fp16 mma, fp32 residuals) =================
__global__ __launch_bounds__(512, 1) void edge_kernel(
    const float* __restrict__ y,
    const float* __restrict__ be,  const float* __restrict__ boe,
    const float* __restrict__ b1,  const float* __restrict__ b2,
    const float* __restrict__ ln4s, const float* __restrict__ ln4b,
    const float* __restrict__ ln6s, const float* __restrict__ ln6b,
    float* __restrict__ yout)
{
    extern __shared__ char smem[];
    __half* sAh = (__half*)smem;                    // 67584
    __half* sRh = (__half*)(smem + 67584);          // 67584
    __half* sHh = (__half*)(smem + 135168);         // 34816
    char*   sBc = smem + 169984;                    // 36864
    float*  sS  = (float*)(smem + 206848);          // 512 f
    float*  sAg = (float*)(smem + 208896);          // 512 f
    float*  sQ  = (float*)(smem + 210944);          // 256 f

    uint32_t sA_u = (uint32_t)__cvta_generic_to_shared(sAh);
    uint32_t sH_u = (uint32_t)__cvta_generic_to_shared(sHh);
    uint32_t sB_u = (uint32_t)__cvta_generic_to_shared(sBc);

    int tid = threadIdx.x, lane = tid & 31, w = tid >> 5;
    int wm = (w >> 2) * 32, wn = w & 3;
    int g = lane >> 2, t = lane & 3;
    int sub = lane >> 3, rin = lane & 7;
    int bi = blockIdx.x, b = bi >> 7;
    const float* yblk = y + (size_t)bi * NTOK * DIMC;

    uint32_t aLaneA = sA_u + (uint32_t)(((wm + (sub&1)*8 + rin)*LDAh + (sub>>1)*8)*2);
    uint32_t aLaneH = sH_u + (uint32_t)(((wm + (sub&1)*8 + rin)*LDHh + (sub>>1)*8)*2);
    uint32_t bLane  = sB_u + (uint32_t)(((wn*32 + (sub&1)*8 + rin)*LDBh + (sub>>1)*8)*2);

    if (tid < 256) sQ[tid] = g_q[bi*DIMC + tid] * ASCALE;
    {
        const float4* y4 = (const float4*)yblk;
        for (int i = tid; i < 8192; i += 512){
            int r = i >> 6, kq = (i & 63) << 2;
            float4 v = y4[i];
            __half2* d = (__half2*)(sAh + r*LDAh + kq);
            d[0] = __floats2half2_rn(v.x, v.y);
            d[1] = __floats2half2_rn(v.z, v.w);
        }
    }

    float cE0[2][4][4], cE1[2][4][4];

    // ---- GEMM1: e = y @ We ----
    ZEROC(cE0, 2, 4); ZEROC(cE1, 2, 4);
    gemm_h(aLaneA, LDAh, g_WeH,            DIMC, 0, 4, sB_u, bLane, cE0, tid);
    gemm_h(aLaneA, LDAh, g_WeH + 128*DIMC, DIMC, 0, 4, sB_u, bLane, cE1, tid);
    __syncthreads();
    #pragma unroll
    for (int nc = 0; nc < 2; nc++)
    #pragma unroll
    for (int mf = 0; mf < 2; mf++)
    #pragma unroll
    for (int nf = 0; nf < 4; nf++)
    #pragma unroll
    for (int hh = 0; hh < 2; hh++){
        float* cc = nc ? cE1[mf][nf] : cE0[mf][nf];
        int r = wm + mf*16 + g + hh*8;
        int col = nc*128 + wn*32 + nf*8 + 2*t;
        float e0 = cc[2*hh+0] + be[col];
        float e1 = cc[2*hh+1] + be[col+1];
        float2 kv = *(const float2*)(g_k + (size_t)(b*NTOK + r)*DIMC + col);
        float v0 = sQ[col]  *kv.x*(e0 + 1.f)*e0;
        float v1 = sQ[col+1]*kv.y*(e1 + 1.f)*e1;
        *(__half2*)(sAh + r*LDAh + col) = __floats2half2_rn(v0, v1);
    }
    __syncthreads();

    // ---- softmax over j + agg ----
    {
        int half_ = tid >> 8, c = tid & 255;
        int j0 = half_*64;
        float mx = -1e30f;
        for (int j = j0; j < j0+64; j++) mx = fmaxf(mx, __half2float(sAh[j*LDAh + c]));
        sS[tid] = mx;
        __syncthreads();
        float M = fmaxf(sS[c], sS[256 + c]);
        float s = 0.f, agv = 0.f;
        for (int j = j0; j < j0+64; j++){
            float p = __expf(__half2float(sAh[j*LDAh + c]) - M);
            s += p;
            agv += p * g_v[(size_t)(b*NTOK + j)*DIMC + c];
        }
        __syncthreads();
        sS[tid] = s; sAg[tid] = agv;
        __syncthreads();
        if (tid < 256)
            g_agg[bi*DIMC + tid] = (sAg[tid] + sAg[256+tid]) / (sS[tid] + sS[256+tid]);
        __syncthreads();
    }

    // ---- GEMM2: edge_out = attn @ Woe ----
    ZEROC(cE0, 2, 4); ZEROC(cE1, 2, 4);
    gemm_h(aLaneA, LDAh, g_WoeH,            DIMC, 0, 4, sB_u, bLane, cE0, tid);
    gemm_h(aLaneA, LDAh, g_WoeH + 128*DIMC, DIMC, 0, 4, sB_u, bLane, cE1, tid);

    // ---- epilogue2 + LN4 in fp32 registers ----
    {
        float ps[2][2] = {}, pq[2][2] = {};
        #pragma unroll
        for (int nc = 0; nc < 2; nc++)
        #pragma unroll
        for (int mf = 0; mf < 2; mf++)
        #pragma unroll
        for (int nf = 0; nf < 4; nf++)
        #pragma unroll
        for (int hh = 0; hh < 2; hh++){
            float* cc = nc ? cE1[mf][nf] : cE0[mf][nf];
            int r = wm + mf*16 + g + hh*8;
            int col = nc*128 + wn*32 + nf*8 + 2*t;
            float2 yv = *(const float2*)(yblk + (size_t)r*DIMC + col);
            float v0 = cc[2*hh+0] + boe[col]   + yv.x;
            float v1 = cc[2*hh+1] + boe[col+1] + yv.y;
            cc[2*hh+0] = v0; cc[2*hh+1] = v1;
            ps[mf][hh] += v0 + v1; pq[mf][hh] += v0*v0 + v1*v1;
        }
        #pragma unroll
        for (int mf = 0; mf < 2; mf++)
        #pragma unroll
        for (int hh = 0; hh < 2; hh++){
            ps[mf][hh] += __shfl_xor_sync(~0u, ps[mf][hh], 1);
            ps[mf][hh] += __shfl_xor_sync(~0u, ps[mf][hh], 2);
            pq[mf][hh] += __shfl_xor_sync(~0u, pq[mf][hh], 1);
            pq[mf][hh] += __shfl_xor_sync(~0u, pq[mf][hh], 2);
        }
        if (t == 0){
            #pragma unroll
            for (int mf = 0; mf < 2; mf++)
            #pragma unroll
            for (int hh = 0; hh < 2; hh++){
                int r = wm + mf*16 + g + hh*8;
                sS [wn*128 + r] = ps[mf][hh];
                sAg[wn*128 + r] = pq[mf][hh];
            }
        }
        __syncthreads();
        #pragma unroll
        for (int mf = 0; mf < 2; mf++)
        #pragma unroll
        for (int hh = 0; hh < 2; hh++){
            int r = wm + mf*16 + g + hh*8;
            float S = sS[r] + sS[128+r] + sS[256+r] + sS[384+r];
            float Q = sAg[r] + sAg[128+r] + sAg[256+r] + sAg[384+r];
            float mean = S * (1.f/256.f);
            float rstd = rsqrtf(Q*(1.f/256.f) - mean*mean + EPSV);
            #pragma unroll
            for (int nc = 0; nc < 2; nc++)
            #pragma unroll
            for (int nf = 0; nf < 4; nf++){
                float* cc = nc ? cE1[mf][nf] : cE0[mf][nf];
                int col = nc*128 + wn*32 + nf*8 + 2*t;
                float v0 = (cc[2*hh+0] - mean)*rstd*ln4s[col]   + ln4b[col];
                float v1 = (cc[2*hh+1] - mean)*rstd*ln4s[col+1] + ln4b[col+1];
                __half h0 = __float2half_rn(v0), h1 = __float2half_rn(v1);
                *(__half2*)(sAh + r*LDAh + col) = __halves2half2(h0, h1);
                *(__half2*)(sRh + r*LDAh + col) =
                    __floats2half2_rn(v0 - __half2float(h0), v1 - __half2float(h1));
            }
        }
    }

    // ---- MLP ----
    float cM0[2][4][4], cM1[2][4][4];
    ZEROC(cM0, 2, 4); ZEROC(cM1, 2, 4);
    for (int ht = 0; ht < 8; ht++){
        float cH[2][4][4];
        ZEROC(cH, 2, 4);
        gemm_h(aLaneA, LDAh, g_W1H + (size_t)ht*128*DIMC, DIMC, 0, 4, sB_u, bLane, cH, tid);
        #pragma unroll
        for (int mf = 0; mf < 2; mf++)
        #pragma unroll
        for (int nf = 0; nf < 4; nf++)
        #pragma unroll
        for (int hh = 0; hh < 2; hh++){
            int r = wm + mf*16 + g + hh*8;
            int col = wn*32 + nf*8 + 2*t;
            float h0 = fmaxf(cH[mf][nf][2*hh+0] + b1[ht*128 + col],     0.f);
            float h1 = fmaxf(cH[mf][nf][2*hh+1] + b1[ht*128 + col + 1], 0.f);
            *(__half2*)(sHh + r*LDHh + col) = __floats2half2_rn(h0, h1);
        }
        gemm_h(aLaneH, LDHh, g_W2H,                   HID, ht*128, 2, sB_u, bLane, cM0, tid);
        gemm_h(aLaneH, LDHh, g_W2H + (size_t)128*HID, HID, ht*128, 2, sB_u, bLane, cM1, tid);
    }

    // ---- LN6 -> yout ----
    {
        float ps[2][2] = {}, pq[2][2] = {};
        #pragma unroll
        for (int nc = 0; nc < 2; nc++)
        #pragma unroll
        for (int mf = 0; mf < 2; mf++)
        #pragma unroll
        for (int nf = 0; nf < 4; nf++)
        #pragma unroll
        for (int hh = 0; hh < 2; hh++){
            float* cc = nc ? cM1[mf][nf] : cM0[mf][nf];
            int r = wm + mf*16 + g + hh*8;
            int col = nc*128 + wn*32 + nf*8 + 2*t;
            float2 hi = __half22float2(*(__half2*)(sAh + r*LDAh + col));
            float2 lo = __half22float2(*(__half2*)(sRh + r*LDAh + col));
            float v0 = cc[2*hh+0] + b2[col]   + hi.x + lo.x;
            float v1 = cc[2*hh+1] + b2[col+1] + hi.y + lo.y;
            cc[2*hh+0] = v0; cc[2*hh+1] = v1;
            ps[mf][hh] += v0 + v1; pq[mf][hh] += v0*v0 + v1*v1;
        }
        #pragma unroll
        for (int mf = 0; mf < 2; mf++)
        #pragma unroll
        for (int hh = 0; hh < 2; hh++){
            ps[mf][hh] += __shfl_xor_sync(~0u, ps[mf][hh], 1);
            ps[mf][hh] += __shfl_xor_sync(~0u, ps[mf][hh], 2);
            pq[mf][hh] += __shfl_xor_sync(~0u, pq[mf][hh], 1);
            pq[mf][hh] += __shfl_xor_sync(~0u, pq[mf][hh], 2);
        }
        __syncthreads();
        if (t == 0){
            #pragma unroll
            for (int mf = 0; mf < 2; mf++)
            #pragma unroll
            for (int hh = 0; hh < 2; hh++){
                int r = wm + mf*16 + g + hh*8;
                sS [wn*128 + r] = ps[mf][hh];
                sAg[wn*128 + r] = pq[mf][hh];
            }
        }
        __syncthreads();
        float* youtb = yout + (size_t)bi*NTOK*DIMC;
        #pragma unroll
        for (int mf = 0; mf < 2; mf++)
        #pragma unroll
        for (int hh = 0; hh < 2; hh++){
            int r = wm + mf*16 + g + hh*8;
            float S = sS[r] + sS[128+r] + sS[256+r] + sS[384+r];
            float Q = sAg[r] + sAg[128+r] + sAg[256+r] + sAg[384+r];
            float mean = S * (1.f/256.f);
            float rstd = rsqrtf(Q*(1.f/256.f) - mean*mean + EPSV);
            #pragma unroll
            for (int nc = 0; nc < 2; nc++)
            #pragma unroll
            for (int nf = 0; nf < 4; nf++){
                float* cc = nc ? cM1[mf][nf] : cM0[mf][nf];
                int col = nc*128 + wn*32 + nf*8 + 2*t;
                float v0 = (cc[2*hh+0] - mean)*rstd*ln6s[col]   + ln6b[col];
                float v1 = (cc[2*hh+1] - mean)*rstd*ln6s[col+1] + ln6b[col+1];
                *(float2*)(youtb + (size_t)r*DIMC + col) = make_float2(v0, v1);
            }
        }
    }
}

// ================= kernel 3: node post (16 rows/CTA, fused MLP rings) =================
__global__ __launch_bounds__(512, 1) void node_post_kernel(
    const float* __restrict__ bon,
    const float* __restrict__ b1, const float* __restrict__ b2,
    const float* __restrict__ ln3s, const float* __restrict__ ln3b,
    const float* __restrict__ ln5s, const float* __restrict__ ln5b,
    float* __restrict__ xout)
{
    extern __shared__ char smp[];
    __half* sA = (__half*)smp;                         // 16*264*2 = 8448
    __half* sH = (__half*)(smp + 8448);                // 16*1032*2 = 33024
    uint32_t sB_u = (uint32_t)__cvta_generic_to_shared(smp + 41472);  // 2*36864
    float* sX   = (float*)(smp + 115200);              // 16*260*4 = 16640
    float* sRed = (float*)(smp + 131840);              // 2*256*4 = 2048
    uint32_t sA_u = (uint32_t)__cvta_generic_to_shared(sA);
    uint32_t sH_u = (uint32_t)__cvta_generic_to_shared(sH);

    int tid = threadIdx.x, lane = tid & 31, w = tid >> 5;   // 16 warps
    int r0 = blockIdx.x * 16;
    int sub = lane >> 3, rin = lane & 7;
    int g = lane >> 2, t2 = (lane & 3)*2;

    for (int i = tid; i < 16*256; i += 512){
        int r = i >> 8, c = i & 255;
        sA[r*LDAh + c] = __float2half_rn(g_agg[(size_t)(r0+r)*DIMC + c]);
    }
    __syncthreads();

    uint32_t aLane   = sA_u + (uint32_t)((((sub&1)*8 + rin)*LDAh + (sub>>1)*8)*2);
    uint32_t hLane2  = sH_u + (uint32_t)((((sub&1)*8 + rin)*LDH2 + (sub>>1)*8)*2);
    uint32_t bLane16 = sB_u + (uint32_t)(((w*16 + (sub&1)*8 + rin)*LDBh + (sub>>1)*8)*2);
    uint32_t bLane8  = sB_u + (uint32_t)(((w*8  + (sub&1)*8 + rin)*LDBh + (sub>>1)*8)*2);

    // GEMM: x2pre = agg @ Won (NF=2, 4 chunks)
    float c1[2][4];
    #pragma unroll
    for (int nf = 0; nf < 2; nf++)
        #pragma unroll
        for (int u = 0; u < 4; u++) c1[nf][u] = 0.f;
    gemm16<2>(aLane, LDAh, g_WonH, DIMC, 0, 4, sB_u, bLane16, c1, tid);

    // epilogue + LN3 (two row groups: g, g+8)
    {
        float v[2][4], ps[2] = {}, pq[2] = {};
        #pragma unroll
        for (int nf = 0; nf < 2; nf++){
            int col = w*16 + nf*8 + t2;
            float2 xA = *(const float2*)(g_x1 + (size_t)(r0+g)*DIMC + col);
            float2 xB = *(const float2*)(g_x1 + (size_t)(r0+g+8)*DIMC + col);
            v[nf][0] = c1[nf][0] + bon[col]   + xA.x;
            v[nf][1] = c1[nf][1] + bon[col+1] + xA.y;
            v[nf][2] = c1[nf][2] + bon[col]   + xB.x;
            v[nf][3] = c1[nf][3] + bon[col+1] + xB.y;
            ps[0] += v[nf][0] + v[nf][1]; pq[0] += v[nf][0]*v[nf][0] + v[nf][1]*v[nf][1];
            ps[1] += v[nf][2] + v[nf][3]; pq[1] += v[nf][2]*v[nf][2] + v[nf][3]*v[nf][3];
        }
        #pragma unroll
        for (int rg = 0; rg < 2; rg++){
            ps[rg] += __shfl_xor_sync(~0u, ps[rg], 1); pq[rg] += __shfl_xor_sync(~0u, pq[rg], 1);
            ps[rg] += __shfl_xor_sync(~0u, ps[rg], 2); pq[rg] += __shfl_xor_sync(~0u, pq[rg], 2);
        }
        if ((lane & 3) == 0){
            sRed[0*256 + w*16 + g]     = ps[0]; sRed[1*256 + w*16 + g]     = pq[0];
            sRed[0*256 + w*16 + g + 8] = ps[1]; sRed[1*256 + w*16 + g + 8] = pq[1];
        }
        __syncthreads();
        #pragma unroll
        for (int rg = 0; rg < 2; rg++){
            int rr = g + rg*8;
            float S = 0.f, Q = 0.f;
            #pragma unroll
            for (int ww = 0; ww < 16; ww++){ S += sRed[0*256 + ww*16 + rr]; Q += sRed[1*256 + ww*16 + rr]; }
            float mean = S * (1.f/256.f);
            float rstd = rsqrtf(Q*(1.f/256.f) - mean*mean + EPSV);
            #pragma unroll
            for (int nf = 0; nf < 2; nf++){
                int col = w*16 + nf*8 + t2;
                float x0 = (v[nf][2*rg+0] - mean)*rstd*ln3s[col]   + ln3b[col];
                float x1 = (v[nf][2*rg+1] - mean)*rstd*ln3s[col+1] + ln3b[col+1];
                sX[rr*260 + col] = x0; sX[rr*260 + col + 1] = x1;
                *(__half2*)(sA + rr*LDAh + col) = __floats2half2_rn(x0, x1);
            }
        }
        __syncthreads();
    }

    // ---- MLP1 fused: 8 panels x 4 chunks, continuous ring; h -> sH (16 x 1024) ----
    #define STGN1(ci) { \
        int _p = (ci) >> 2, _kc = (ci) & 3; \
        const __half* _s = g_N1H + (size_t)(_p*128)*DIMC + _kc*KCH; \
        uint32_t _d = sB_u + (uint32_t)((ci)&1)*BUFSZ2; \
        _Pragma("unroll") \
        for (int _j = 0; _j < 2; _j++){ \
            int _ii = tid + _j*512; \
            int _n = _ii >> 3, _q = _ii & 7; \
            cpa16(_d + (uint32_t)(_n*LDBh + _q*8)*2, _s + (size_t)_n*DIMC + _q*8); \
        } \
        CP_COMMIT(); }
    {
        float cH[4] = {0.f, 0.f, 0.f, 0.f};
        STGN1(0);
        for (int ci = 0; ci < 32; ci++){
            int kc = ci & 3, p = ci >> 2;
            __syncthreads();
            if (ci + 1 < 32){ STGN1(ci+1); CP_WAIT(1); }
            else            { CP_WAIT(0); }
            __syncthreads();
            uint32_t bBuf = bLane8 + (uint32_t)(ci & 1)*BUFSZ2;
            #pragma unroll
            for (int ks = 0; ks < 4; ks++){
                uint32_t a[4];
                ldsm4(a, aLane + (uint32_t)((kc*KCH + ks*16))*2);
                uint32_t b4[4];
                ldsm4(b4, bBuf + (uint32_t)(ks*16)*2);
                uint32_t bx[2] = { b4[0], b4[2] };
                mma16(cH, a, bx);
            }
            if (kc == 3){
                int col = p*128 + w*8 + t2;
                *(__half2*)(sH + g*LDH2 + col) = __floats2half2_rn(
                    fmaxf(cH[0] + b1[col],     0.f),
                    fmaxf(cH[1] + b1[col + 1], 0.f));
                *(__half2*)(sH + (g+8)*LDH2 + col) = __floats2half2_rn(
                    fmaxf(cH[2] + b1[col],     0.f),
                    fmaxf(cH[3] + b1[col + 1], 0.f));
                cH[0] = cH[1] = cH[2] = cH[3] = 0.f;
            }
        }
    }
    #undef STGN1

    // ---- MLP2: one gemm over full K=1024 (16 chunks) ----
    float cM[2][4];
    #pragma unroll
    for (int nf = 0; nf < 2; nf++)
        #pragma unroll
        for (int u = 0; u < 4; u++) cM[nf][u] = 0.f;
    gemm16<2>(hLane2, LDH2, g_N2H, HID, 0, 16, sB_u, bLane16, cM, tid);

    // final: out = cM + b2 + x2 ; LN5 -> xout (two row groups)
    {
        float v[2][4], ps[2] = {}, pq[2] = {};
        #pragma unroll
        for (int nf = 0; nf < 2; nf++){
            int col = w*16 + nf*8 + t2;
            v[nf][0] = cM[nf][0] + b2[col]   + sX[g*260 + col];
            v[nf][1] = cM[nf][1] + b2[col+1] + sX[g*260 + col + 1];
            v[nf][2] = cM[nf][2] + b2[col]   + sX[(g+8)*260 + col];
            v[nf][3] = cM[nf][3] + b2[col+1] + sX[(g+8)*260 + col + 1];
            ps[0] += v[nf][0] + v[nf][1]; pq[0] += v[nf][0]*v[nf][0] + v[nf][1]*v[nf][1];
            ps[1] += v[nf][2] + v[nf][3]; pq[1] += v[nf][2]*v[nf][2] + v[nf][3]*v[nf][3];
        }
        #pragma unroll
        for (int rg = 0; rg < 2; rg++){
            ps[rg] += __shfl_xor_sync(~0u, ps[rg], 1); pq[rg] += __shfl_xor_sync(~0u, pq[rg], 1);
            ps[rg] += __shfl_xor_sync(~0u, ps[rg], 2); pq[rg] += __shfl_xor_sync(~0u, pq[rg], 2);
        }
        __syncthreads();
        if ((lane & 3) == 0){
            sRed[0*256 + w*16 + g]     = ps[0]; sRed[1*256 + w*16 + g]     = pq[0];
            sRed[0*256 + w*16 + g + 8] = ps[1]; sRed[1*256 + w*16 + g + 8] = pq[1];
        }
        __syncthreads();
        #pragma unroll
        for (int rg = 0; rg < 2; rg++){
            int rr = g + rg*8;
            float S = 0.f, Q = 0.f;
            #pragma unroll
            for (int ww = 0; ww < 16; ww++){ S += sRed[0*256 + ww*16 + rr]; Q += sRed[1*256 + ww*16 + rr]; }
            float mean = S * (1.f/256.f);
            float rstd = rsqrtf(Q*(1.f/256.f) - mean*mean + EPSV);
            #pragma unroll
            for (int nf = 0; nf < 2; nf++){
                int col = w*16 + nf*8 + t2;
                float o0 = (v[nf][2*rg+0] - mean)*rstd*ln5s[col]   + ln5b[col];
                float o1 = (v[nf][2*rg+1] - mean)*rstd*ln5s[col+1] + ln5b[col+1];
                *(float2*)(xout + (size_t)(r0+rr)*DIMC + col) = make_float2(o0, o1);
            }
        }
    }
}

// ================= launch =================
extern "C" void kernel_launch(void* const* d_in, const int* in_sizes, int n_in,
                              void* d_out, int out_size)
{
    const float* x    = (const float*)d_in[0];
    const float* y    = (const float*)d_in[1];
    const float* Wq   = (const float*)d_in[2];  const float* bq  = (const float*)d_in[3];
    const float* Wk   = (const float*)d_in[4];  const float* bk  = (const float*)d_in[5];
    const float* Wv   = (const float*)d_in[6];  const float* bv  = (const float*)d_in[7];
    const float* We   = (const float*)d_in[8];  const float* be  = (const float*)d_in[9];
    const float* Woe  = (const float*)d_in[10]; const float* boe = (const float*)d_in[11];
    const float* Won  = (const float*)d_in[12]; const float* bon = (const float*)d_in[13];
    const float* m1w1 = (const float*)d_in[14]; const float* m1b1= (const float*)d_in[15];
    const float* m1w2 = (const float*)d_in[16]; const float* m1b2= (const float*)d_in[17];
    const float* m2w1 = (const float*)d_in[18]; const float* m2b1= (const float*)d_in[19];
    const float* m2w2 = (const float*)d_in[20]; const float* m2b2= (const float*)d_in[21];
    const float* ln1s = (const float*)d_in[22]; const float* ln1b= (const float*)d_in[23];
    const float* ln3s = (const float*)d_in[24]; const float* ln3b= (const float*)d_in[25];
    const float* ln4s = (const float*)d_in[26]; const float* ln4b= (const float*)d_in[27];
    const float* ln5s = (const float*)d_in[28]; const float* ln5b= (const float*)d_in[29];
    const float* ln6s = (const float*)d_in[30]; const float* ln6b= (const float*)d_in[31];

    float* out  = (float*)d_out;
    float* xout = out;                               // (8,128,256)
    float* yout = out + BAT*NTOK*DIMC;               // (8,128,128,256)

    int smemE = 211968;
    int smemPre  = 8448 + 2*BUFSZ2;                  // 82176
    int smemPost = 133888;
    cudaFuncSetAttribute(edge_kernel, cudaFuncAttributeMaxDynamicSharedMemorySize, smemE);
    cudaFuncSetAttribute(node_pre_kernel, cudaFuncAttributeMaxDynamicSharedMemorySize, smemPre);
    cudaFuncSetAttribute(node_post_kernel, cudaFuncAttributeMaxDynamicSharedMemorySize, smemPost);

    prep_kernel<<<1024, 256>>>(We, Woe, m2w1, m2w2, m1w1, m1w2, Won, Wq, Wk, Wv);
    node_pre_kernel<<<BAT*NTOK/16, 512, smemPre>>>(x, bq, bk, bv, ln1s, ln1b);
    edge_kernel<<<BAT*NTOK, 512, smemE>>>(y, be, boe, m2b1, m2b2,
                                          ln4s, ln4b, ln6s, ln6b, yout);
    node_post_kernel<<<BAT*NTOK/16, 512, smemPost>>>(bon, m1b1, m1b2,
                                                     ln3s, ln3b, ln5s, ln5b, xout);
}